// round 2
// baseline (speedup 1.0000x reference)
#include <cuda_runtime.h>
#include <math.h>

// ---------------- scratch (device globals: allocation-guard safe) ----------
__device__ float g_qkv[(size_t)8192 * 3072];   // [B*T, 3C]  Q|K|V packed per row
__device__ float g_y  [(size_t)8192 * 1024];   // [B*T, C]   attention output

// ---------------- SGEMM 128x128x8, 256 threads, 8x8 per thread -------------
__global__ void __launch_bounds__(256) sgemm_bias_kernel(
    const float* __restrict__ A,   // [M,K] row-major
    const float* __restrict__ B,   // [K,N] row-major
    const float* __restrict__ bias,// [N]
    float* __restrict__ C,         // [M,N]
    int M, int N, int K)
{
    __shared__ float As[8][128];   // As[k][m]
    __shared__ float Bs[8][128];   // Bs[k][n]

    const int tid = threadIdx.x;
    const int bx = blockIdx.x;     // N tile
    const int by = blockIdx.y;     // M tile

    const int aRow  = tid >> 1;            // 0..127
    const int aCol4 = (tid & 1) << 2;      // 0 or 4
    const int bRow  = tid >> 5;            // 0..7
    const int bCol4 = (tid & 31) << 2;     // 0..124

    const float* Ab = A + (size_t)(by * 128) * K;
    const float* Bb = B + bx * 128;

    const int tx = tid & 15;   // col group
    const int ty = tid >> 4;   // row group

    float acc[8][8];
#pragma unroll
    for (int i = 0; i < 8; i++)
#pragma unroll
        for (int j = 0; j < 8; j++) acc[i][j] = 0.0f;

    for (int k0 = 0; k0 < K; k0 += 8) {
        float4 a4 = *(const float4*)(Ab + (size_t)aRow * K + k0 + aCol4);
        As[aCol4 + 0][aRow] = a4.x;
        As[aCol4 + 1][aRow] = a4.y;
        As[aCol4 + 2][aRow] = a4.z;
        As[aCol4 + 3][aRow] = a4.w;
        float4 b4 = *(const float4*)(Bb + (size_t)(k0 + bRow) * N + bCol4);
        *(float4*)(&Bs[bRow][bCol4]) = b4;
        __syncthreads();

#pragma unroll
        for (int kk = 0; kk < 8; kk++) {
            float ar[8], br[8];
            *(float4*)(ar)     = *(const float4*)(&As[kk][ty * 8]);
            *(float4*)(ar + 4) = *(const float4*)(&As[kk][ty * 8 + 4]);
            *(float4*)(br)     = *(const float4*)(&Bs[kk][tx * 8]);
            *(float4*)(br + 4) = *(const float4*)(&Bs[kk][tx * 8 + 4]);
#pragma unroll
            for (int i = 0; i < 8; i++)
#pragma unroll
                for (int j = 0; j < 8; j++)
                    acc[i][j] = fmaf(ar[i], br[j], acc[i][j]);
        }
        __syncthreads();
    }

    const int row0 = by * 128 + ty * 8;
    const int col0 = bx * 128 + tx * 8;
    float4 bia0 = *(const float4*)(bias + col0);
    float4 bia1 = *(const float4*)(bias + col0 + 4);
#pragma unroll
    for (int i = 0; i < 8; i++) {
        float4 o0, o1;
        o0.x = acc[i][0] + bia0.x; o0.y = acc[i][1] + bia0.y;
        o0.z = acc[i][2] + bia0.z; o0.w = acc[i][3] + bia0.w;
        o1.x = acc[i][4] + bia1.x; o1.y = acc[i][5] + bia1.y;
        o1.z = acc[i][6] + bia1.z; o1.w = acc[i][7] + bia1.w;
        *(float4*)(C + (size_t)(row0 + i) * N + col0)     = o0;
        *(float4*)(C + (size_t)(row0 + i) * N + col0 + 4) = o1;
    }
}

// ---------------- attention: 64q x 64k tiles, fp32 flash ------------------
// Mask semantics (must match reference bit-behavior):
//   q <  l : causal, masked entries -> exp underflows to 0 (use -1e30 sentinel)
//   q >= l : attend to ALL k but add -1e8f in fp32 (quantizes logits to the
//            fp32 grid at 1e8 exactly like the reference's additive mask)
#define ALDS 68   // padded row stride (floats)

__global__ void __launch_bounds__(256) attn_kernel(
    const float* __restrict__ qkv,  // [B*T, 3072]; Q at col h*64, K +1024, V +2048
    const int*   __restrict__ lv,   // [B]
    float* __restrict__ y)          // [B*T, 1024]
{
    extern __shared__ float sm[];
    float* QsT = sm;                 // [64][ALDS]  QsT[d][r]
    float* KsT = QsT + 64 * ALDS;    // [64][ALDS]  KsT[d][c]
    float* Vs  = KsT + 64 * ALDS;    // [64][ALDS]  Vs[c][d]
    float* Ss  = Vs  + 64 * ALDS;    // [64][ALDS]  Ss[c][r]  (S transposed, then P)
    float* m_s = Ss  + 64 * ALDS;    // [64]
    float* l_s = m_s + 64;           // [64]
    float* a_s = l_s + 64;           // [64]

    const int tid = threadIdx.x;
    const int bh  = blockIdx.y;
    const int b   = bh >> 4;
    const int h   = bh & 15;
    const int q0  = blockIdx.x * 64;
    const int lb  = lv[b];

    const float* Qb = qkv + (size_t)b * 2048 * 3072 + h * 64;
    const float* Kb = Qb + 1024;
    const float* Vb = Qb + 2048;

    // load Q tile (transposed into QsT[d][r])
    for (int i = tid; i < 64 * 16; i += 256) {
        int r  = i >> 4;
        int d4 = (i & 15) << 2;
        float4 v = *(const float4*)(Qb + (size_t)(q0 + r) * 3072 + d4);
        QsT[(d4 + 0) * ALDS + r] = v.x;
        QsT[(d4 + 1) * ALDS + r] = v.y;
        QsT[(d4 + 2) * ALDS + r] = v.z;
        QsT[(d4 + 3) * ALDS + r] = v.w;
    }
    if (tid < 64) { m_s[tid] = -1e30f; l_s[tid] = 0.0f; }

    const int tx = tid & 15;       // key-col / out-d group
    const int ty = tid >> 4;       // query-row group
    const int r0 = ty * 4;
    const int c0 = tx * 4;

    float acc[4][4];
#pragma unroll
    for (int i = 0; i < 4; i++)
#pragma unroll
        for (int j = 0; j < 4; j++) acc[i][j] = 0.0f;

    // causal-only block iff all its rows have q < lb
    const int nTiles = (q0 + 64 <= lb) ? (blockIdx.x + 1) : 32;

    for (int t = 0; t < nTiles; t++) {
        const int k0 = t * 64;
        __syncthreads();   // Q ready (iter 0) / prev PV done before K,V,Ss overwrite

        for (int i = tid; i < 64 * 16; i += 256) {
            int c  = i >> 4;
            int d4 = (i & 15) << 2;
            float4 kk4 = *(const float4*)(Kb + (size_t)(k0 + c) * 3072 + d4);
            KsT[(d4 + 0) * ALDS + c] = kk4.x;
            KsT[(d4 + 1) * ALDS + c] = kk4.y;
            KsT[(d4 + 2) * ALDS + c] = kk4.z;
            KsT[(d4 + 3) * ALDS + c] = kk4.w;
            float4 vv4 = *(const float4*)(Vb + (size_t)(k0 + c) * 3072 + d4);
            *(float4*)(Vs + c * ALDS + d4) = vv4;
        }
        __syncthreads();

        // S = Q K^T (rank-1 updates over d)
        float s[4][4];
#pragma unroll
        for (int i = 0; i < 4; i++)
#pragma unroll
            for (int j = 0; j < 4; j++) s[i][j] = 0.0f;

#pragma unroll 8
        for (int kk = 0; kk < 64; kk++) {
            float4 qa = *(const float4*)(QsT + kk * ALDS + r0);
            float4 kb = *(const float4*)(KsT + kk * ALDS + c0);
            float qr[4] = {qa.x, qa.y, qa.z, qa.w};
            float kr[4] = {kb.x, kb.y, kb.z, kb.w};
#pragma unroll
            for (int i = 0; i < 4; i++)
#pragma unroll
                for (int j = 0; j < 4; j++)
                    s[i][j] = fmaf(qr[i], kr[j], s[i][j]);
        }

        // mask + write S transposed
#pragma unroll
        for (int i = 0; i < 4; i++) {
            const int qg = q0 + r0 + i;
#pragma unroll
            for (int j = 0; j < 4; j++) {
                const int kg = k0 + c0 + j;
                float v = s[i][j] * 0.125f;
                if (qg < lb) {
                    if (kg > qg) v = -1e30f;
                } else {
                    v = v + (-1e8f);   // fp32 add: replicates reference quantization
                }
                Ss[(c0 + j) * ALDS + (r0 + i)] = v;
            }
        }
        __syncthreads();

        // per-row online-softmax stats (one thread per row)
        if (tid < 64) {
            const int r = tid;
            float mx = -1e30f;
#pragma unroll 8
            for (int c = 0; c < 64; c++)
                mx = fmaxf(mx, Ss[c * ALDS + r]);
            const float m_old = m_s[r];
            const float m_new = fmaxf(m_old, mx);
            const float alpha = __expf(m_old - m_new);
            float sum = 0.0f;
#pragma unroll 8
            for (int c = 0; c < 64; c++) {
                float e = __expf(Ss[c * ALDS + r] - m_new);
                Ss[c * ALDS + r] = e;
                sum += e;
            }
            l_s[r] = l_s[r] * alpha + sum;
            m_s[r] = m_new;
            a_s[r] = alpha;
        }
        __syncthreads();

        // rescale accumulators, then O += P V
        float al[4];
#pragma unroll
        for (int i = 0; i < 4; i++) al[i] = a_s[r0 + i];
#pragma unroll
        for (int i = 0; i < 4; i++)
#pragma unroll
            for (int j = 0; j < 4; j++) acc[i][j] *= al[i];

#pragma unroll 8
        for (int c = 0; c < 64; c++) {
            float4 pr = *(const float4*)(Ss + c * ALDS + r0);
            float4 vv = *(const float4*)(Vs + c * ALDS + c0);
            float p[4] = {pr.x, pr.y, pr.z, pr.w};
            float vr[4] = {vv.x, vv.y, vv.z, vv.w};
#pragma unroll
            for (int i = 0; i < 4; i++)
#pragma unroll
                for (int j = 0; j < 4; j++)
                    acc[i][j] = fmaf(p[i], vr[j], acc[i][j]);
        }
    }

    // write O / l  -> y[b*T + q][h*64 + d]
    float inv[4];
#pragma unroll
    for (int i = 0; i < 4; i++) inv[i] = 1.0f / l_s[r0 + i];
#pragma unroll
    for (int i = 0; i < 4; i++) {
        float4 o;
        o.x = acc[i][0] * inv[i];
        o.y = acc[i][1] * inv[i];
        o.z = acc[i][2] * inv[i];
        o.w = acc[i][3] * inv[i];
        *(float4*)(y + (size_t)(b * 2048 + q0 + r0 + i) * 1024 + h * 64 + c0) = o;
    }
}

// ---------------- launch ---------------------------------------------------
static const int ATTN_SMEM = (4 * 64 * ALDS + 3 * 64) * (int)sizeof(float);

extern "C" void kernel_launch(void* const* d_in, const int* in_sizes, int n_in,
                              void* d_out, int out_size)
{
    const float* x      = (const float*)d_in[0];  // [4,2048,1024]
    const int*   l      = (const int*)  d_in[1];  // [4]
    const float* W_attn = (const float*)d_in[2];  // [1024,3072]
    const float* b_attn = (const float*)d_in[3];  // [3072]
    const float* W_proj = (const float*)d_in[4];  // [1024,1024]
    const float* b_proj = (const float*)d_in[5];  // [1024]
    float* out = (float*)d_out;                   // [4,2048,1024]

    float* qkv = nullptr;
    float* yb  = nullptr;
    cudaGetSymbolAddress((void**)&qkv, g_qkv);
    cudaGetSymbolAddress((void**)&yb,  g_y);

    cudaFuncSetAttribute(attn_kernel,
                         cudaFuncAttributeMaxDynamicSharedMemorySize, ATTN_SMEM);

    // 1) QKV = x @ W_attn + b_attn
    {
        dim3 grid(3072 / 128, 8192 / 128);
        sgemm_bias_kernel<<<grid, 256>>>(x, W_attn, b_attn, qkv, 8192, 3072, 1024);
    }
    // 2) attention
    {
        dim3 grid(2048 / 64, 4 * 16);
        attn_kernel<<<grid, 256, ATTN_SMEM>>>(qkv, l, yb);
    }
    // 3) out = y @ W_proj + b_proj
    {
        dim3 grid(1024 / 128, 8192 / 128);
        sgemm_bias_kernel<<<grid, 256>>>(yb, W_proj, b_proj, out, 8192, 1024, 1024);
    }
}

// round 3
// speedup vs baseline: 1.4395x; 1.4395x over previous
#include <cuda_runtime.h>
#include <math.h>

// ---------------- scratch (device globals: allocation-guard safe) ----------
__device__ float g_qkv[(size_t)8192 * 3072];   // [B*T, 3C]  Q|K|V packed per row
__device__ float g_y  [(size_t)8192 * 1024];   // [B*T, C]   attention output

// ---------------- tf32 helpers ---------------------------------------------
__device__ __forceinline__ unsigned f2tf(float f) {
    unsigned u;
    asm("cvt.rna.tf32.f32 %0, %1;" : "=r"(u) : "f"(f));
    return u;
}

#define MMA_TF32(d, av, bv)                                                   \
    asm volatile(                                                             \
        "mma.sync.aligned.m16n8k8.row.col.f32.tf32.tf32.f32 "                 \
        "{%0,%1,%2,%3},{%4,%5,%6,%7},{%8,%9},{%0,%1,%2,%3};"                  \
        : "+f"(d[0]), "+f"(d[1]), "+f"(d[2]), "+f"(d[3])                      \
        : "r"(av[0]), "r"(av[1]), "r"(av[2]), "r"(av[3]),                     \
          "r"(bv[0]), "r"(bv[1]))

// ---------------- tf32 SGEMM 128x128x16, 256 threads, tensor cores ---------
// C[M,N] = A[M,K] @ B[K,N] + bias, A/B row-major, M%128==0, N%128==0, K%16==0
#define SA 132   // padded smem stride (floats)

__global__ void __launch_bounds__(256, 2) sgemm_tf32_kernel(
    const float* __restrict__ A,
    const float* __restrict__ B,
    const float* __restrict__ bias,
    float* __restrict__ C,
    int M, int N, int K)
{
    __shared__ unsigned AsU[2][16 * SA];   // [k][m] (tf32 bits)
    __shared__ unsigned BsU[2][16 * SA];   // [k][n] (tf32 bits)

    const int tid  = threadIdx.x;
    const int lane = tid & 31;
    const int wid  = tid >> 5;
    const int bx   = blockIdx.x;     // N tile
    const int by   = blockIdx.y;     // M tile

    const int warp_m = wid & 1;      // 0..1 -> 64-row slab
    const int warp_n = wid >> 1;     // 0..3 -> 32-col slab
    const int g  = lane >> 2;        // group (0..7)
    const int tg = lane & 3;         // thread-in-group (0..3)

    // staging index maps (coalesced 64B per 8-lane group)
    const int amRow = tid >> 2;            // 0..63 (and +64)
    const int akc   = (tid & 3) << 2;      // 0,4,8,12
    const int bkr   = tid >> 5;            // 0..7 (and +8)
    const int bnc   = (tid & 31) << 2;     // 0..124

    const float* Ab = A + (size_t)(by * 128) * K;
    const float* Bb = B + bx * 128;

    float acc[4][4][4];
#pragma unroll
    for (int i = 0; i < 4; i++)
#pragma unroll
        for (int j = 0; j < 4; j++)
#pragma unroll
            for (int r = 0; r < 4; r++) acc[i][j][r] = 0.0f;

    // ---- prologue: load tile k0=0, stage into buf 0
    float4 ra0 = *(const float4*)(Ab + (size_t)amRow * K + akc);
    float4 ra1 = *(const float4*)(Ab + (size_t)(amRow + 64) * K + akc);
    float4 rb0 = *(const float4*)(Bb + (size_t)bkr * N + bnc);
    float4 rb1 = *(const float4*)(Bb + (size_t)(bkr + 8) * N + bnc);
    {
        AsU[0][(akc + 0) * SA + amRow] = f2tf(ra0.x);
        AsU[0][(akc + 1) * SA + amRow] = f2tf(ra0.y);
        AsU[0][(akc + 2) * SA + amRow] = f2tf(ra0.z);
        AsU[0][(akc + 3) * SA + amRow] = f2tf(ra0.w);
        AsU[0][(akc + 0) * SA + amRow + 64] = f2tf(ra1.x);
        AsU[0][(akc + 1) * SA + amRow + 64] = f2tf(ra1.y);
        AsU[0][(akc + 2) * SA + amRow + 64] = f2tf(ra1.z);
        AsU[0][(akc + 3) * SA + amRow + 64] = f2tf(ra1.w);
        BsU[0][bkr * SA + bnc + 0] = f2tf(rb0.x);
        BsU[0][bkr * SA + bnc + 1] = f2tf(rb0.y);
        BsU[0][bkr * SA + bnc + 2] = f2tf(rb0.z);
        BsU[0][bkr * SA + bnc + 3] = f2tf(rb0.w);
        BsU[0][(bkr + 8) * SA + bnc + 0] = f2tf(rb1.x);
        BsU[0][(bkr + 8) * SA + bnc + 1] = f2tf(rb1.y);
        BsU[0][(bkr + 8) * SA + bnc + 2] = f2tf(rb1.z);
        BsU[0][(bkr + 8) * SA + bnc + 3] = f2tf(rb1.w);
    }
    __syncthreads();

    int buf = 0;
    for (int k0 = 0; k0 < K; k0 += 16) {
        const bool hasNext = (k0 + 16) < K;
        if (hasNext) {
            const float* An = Ab + k0 + 16;
            const float* Bn = Bb + (size_t)(k0 + 16) * N;
            ra0 = *(const float4*)(An + (size_t)amRow * K + akc);
            ra1 = *(const float4*)(An + (size_t)(amRow + 64) * K + akc);
            rb0 = *(const float4*)(Bn + (size_t)bkr * N + bnc);
            rb1 = *(const float4*)(Bn + (size_t)(bkr + 8) * N + bnc);
        }

        const unsigned* As = AsU[buf];
        const unsigned* Bs = BsU[buf];
#pragma unroll
        for (int ks = 0; ks < 16; ks += 8) {
            unsigned af[4][4], bf[4][2];
#pragma unroll
            for (int i = 0; i < 4; i++) {
                const int m = warp_m * 64 + i * 16 + g;
                af[i][0] = As[(ks + tg) * SA + m];
                af[i][1] = As[(ks + tg) * SA + m + 8];
                af[i][2] = As[(ks + tg + 4) * SA + m];
                af[i][3] = As[(ks + tg + 4) * SA + m + 8];
            }
#pragma unroll
            for (int j = 0; j < 4; j++) {
                const int n = warp_n * 32 + j * 8 + g;
                bf[j][0] = Bs[(ks + tg) * SA + n];
                bf[j][1] = Bs[(ks + tg + 4) * SA + n];
            }
#pragma unroll
            for (int i = 0; i < 4; i++)
#pragma unroll
                for (int j = 0; j < 4; j++)
                    MMA_TF32(acc[i][j], af[i], bf[j]);
        }

        if (hasNext) {
            const int nb = buf ^ 1;
            AsU[nb][(akc + 0) * SA + amRow] = f2tf(ra0.x);
            AsU[nb][(akc + 1) * SA + amRow] = f2tf(ra0.y);
            AsU[nb][(akc + 2) * SA + amRow] = f2tf(ra0.z);
            AsU[nb][(akc + 3) * SA + amRow] = f2tf(ra0.w);
            AsU[nb][(akc + 0) * SA + amRow + 64] = f2tf(ra1.x);
            AsU[nb][(akc + 1) * SA + amRow + 64] = f2tf(ra1.y);
            AsU[nb][(akc + 2) * SA + amRow + 64] = f2tf(ra1.z);
            AsU[nb][(akc + 3) * SA + amRow + 64] = f2tf(ra1.w);
            BsU[nb][bkr * SA + bnc + 0] = f2tf(rb0.x);
            BsU[nb][bkr * SA + bnc + 1] = f2tf(rb0.y);
            BsU[nb][bkr * SA + bnc + 2] = f2tf(rb0.z);
            BsU[nb][bkr * SA + bnc + 3] = f2tf(rb0.w);
            BsU[nb][(bkr + 8) * SA + bnc + 0] = f2tf(rb1.x);
            BsU[nb][(bkr + 8) * SA + bnc + 1] = f2tf(rb1.y);
            BsU[nb][(bkr + 8) * SA + bnc + 2] = f2tf(rb1.z);
            BsU[nb][(bkr + 8) * SA + bnc + 3] = f2tf(rb1.w);
        }
        __syncthreads();
        buf ^= 1;
    }

    // ---- epilogue: bias + store (float2 per row-pair per tile)
#pragma unroll
    for (int i = 0; i < 4; i++) {
        const int row = by * 128 + warp_m * 64 + i * 16 + g;
#pragma unroll
        for (int j = 0; j < 4; j++) {
            const int col = bx * 128 + warp_n * 32 + j * 8 + tg * 2;
            const float2 bv = *(const float2*)(bias + col);
            float2 o0, o1;
            o0.x = acc[i][j][0] + bv.x; o0.y = acc[i][j][1] + bv.y;
            o1.x = acc[i][j][2] + bv.x; o1.y = acc[i][j][3] + bv.y;
            *(float2*)(C + (size_t)row * N + col)       = o0;
            *(float2*)(C + (size_t)(row + 8) * N + col) = o1;
        }
    }
}

// ---------------- attention: 64q x 64k tiles, fp32 flash ------------------
// Mask semantics (must match reference bit-behavior):
//   q <  l : causal, masked entries -> exp underflows to 0 (use -1e30 sentinel)
//   q >= l : attend to ALL k but add -1e8f in fp32 (quantizes logits to the
//            fp32 grid at 1e8 exactly like the reference's additive mask)
#define ALDS 68   // padded row stride (floats)

__global__ void __launch_bounds__(256) attn_kernel(
    const float* __restrict__ qkv,  // [B*T, 3072]; Q at col h*64, K +1024, V +2048
    const int*   __restrict__ lv,   // [B]
    float* __restrict__ y)          // [B*T, 1024]
{
    extern __shared__ float sm[];
    float* QsT = sm;                 // [64][ALDS]  QsT[d][r]
    float* KsT = QsT + 64 * ALDS;    // [64][ALDS]  KsT[d][c]
    float* Vs  = KsT + 64 * ALDS;    // [64][ALDS]  Vs[c][d]
    float* Ss  = Vs  + 64 * ALDS;    // [64][ALDS]  Ss[c][r]  (S transposed, then P)
    float* m_s = Ss  + 64 * ALDS;    // [64]
    float* l_s = m_s + 64;           // [64]
    float* a_s = l_s + 64;           // [64]

    const int tid = threadIdx.x;
    const int bh  = blockIdx.y;
    const int b   = bh >> 4;
    const int h   = bh & 15;
    const int q0  = blockIdx.x * 64;
    const int lb  = lv[b];

    const float* Qb = qkv + (size_t)b * 2048 * 3072 + h * 64;
    const float* Kb = Qb + 1024;
    const float* Vb = Qb + 2048;

    // load Q tile (transposed into QsT[d][r])
    for (int i = tid; i < 64 * 16; i += 256) {
        int r  = i >> 4;
        int d4 = (i & 15) << 2;
        float4 v = *(const float4*)(Qb + (size_t)(q0 + r) * 3072 + d4);
        QsT[(d4 + 0) * ALDS + r] = v.x;
        QsT[(d4 + 1) * ALDS + r] = v.y;
        QsT[(d4 + 2) * ALDS + r] = v.z;
        QsT[(d4 + 3) * ALDS + r] = v.w;
    }
    if (tid < 64) { m_s[tid] = -1e30f; l_s[tid] = 0.0f; }

    const int tx = tid & 15;       // key-col / out-d group
    const int ty = tid >> 4;       // query-row group
    const int r0 = ty * 4;
    const int c0 = tx * 4;

    float acc[4][4];
#pragma unroll
    for (int i = 0; i < 4; i++)
#pragma unroll
        for (int j = 0; j < 4; j++) acc[i][j] = 0.0f;

    // causal-only block iff all its rows have q < lb
    const int nTiles = (q0 + 64 <= lb) ? (blockIdx.x + 1) : 32;

    for (int t = 0; t < nTiles; t++) {
        const int k0 = t * 64;
        __syncthreads();   // Q ready (iter 0) / prev PV done before K,V,Ss overwrite

        for (int i = tid; i < 64 * 16; i += 256) {
            int c  = i >> 4;
            int d4 = (i & 15) << 2;
            float4 kk4 = *(const float4*)(Kb + (size_t)(k0 + c) * 3072 + d4);
            KsT[(d4 + 0) * ALDS + c] = kk4.x;
            KsT[(d4 + 1) * ALDS + c] = kk4.y;
            KsT[(d4 + 2) * ALDS + c] = kk4.z;
            KsT[(d4 + 3) * ALDS + c] = kk4.w;
            float4 vv4 = *(const float4*)(Vb + (size_t)(k0 + c) * 3072 + d4);
            *(float4*)(Vs + c * ALDS + d4) = vv4;
        }
        __syncthreads();

        // S = Q K^T (rank-1 updates over d)
        float s[4][4];
#pragma unroll
        for (int i = 0; i < 4; i++)
#pragma unroll
            for (int j = 0; j < 4; j++) s[i][j] = 0.0f;

#pragma unroll 8
        for (int kk = 0; kk < 64; kk++) {
            float4 qa = *(const float4*)(QsT + kk * ALDS + r0);
            float4 kb = *(const float4*)(KsT + kk * ALDS + c0);
            float qr[4] = {qa.x, qa.y, qa.z, qa.w};
            float kr[4] = {kb.x, kb.y, kb.z, kb.w};
#pragma unroll
            for (int i = 0; i < 4; i++)
#pragma unroll
                for (int j = 0; j < 4; j++)
                    s[i][j] = fmaf(qr[i], kr[j], s[i][j]);
        }

        // mask + write S transposed
#pragma unroll
        for (int i = 0; i < 4; i++) {
            const int qg = q0 + r0 + i;
#pragma unroll
            for (int j = 0; j < 4; j++) {
                const int kg = k0 + c0 + j;
                float v = s[i][j] * 0.125f;
                if (qg < lb) {
                    if (kg > qg) v = -1e30f;
                } else {
                    v = v + (-1e8f);   // fp32 add: replicates reference quantization
                }
                Ss[(c0 + j) * ALDS + (r0 + i)] = v;
            }
        }
        __syncthreads();

        // per-row online-softmax stats (one thread per row)
        if (tid < 64) {
            const int r = tid;
            float mx = -1e30f;
#pragma unroll 8
            for (int c = 0; c < 64; c++)
                mx = fmaxf(mx, Ss[c * ALDS + r]);
            const float m_old = m_s[r];
            const float m_new = fmaxf(m_old, mx);
            const float alpha = __expf(m_old - m_new);
            float sum = 0.0f;
#pragma unroll 8
            for (int c = 0; c < 64; c++) {
                float e = __expf(Ss[c * ALDS + r] - m_new);
                Ss[c * ALDS + r] = e;
                sum += e;
            }
            l_s[r] = l_s[r] * alpha + sum;
            m_s[r] = m_new;
            a_s[r] = alpha;
        }
        __syncthreads();

        // rescale accumulators, then O += P V
        float al[4];
#pragma unroll
        for (int i = 0; i < 4; i++) al[i] = a_s[r0 + i];
#pragma unroll
        for (int i = 0; i < 4; i++)
#pragma unroll
            for (int j = 0; j < 4; j++) acc[i][j] *= al[i];

#pragma unroll 8
        for (int c = 0; c < 64; c++) {
            float4 pr = *(const float4*)(Ss + c * ALDS + r0);
            float4 vv = *(const float4*)(Vs + c * ALDS + c0);
            float p[4] = {pr.x, pr.y, pr.z, pr.w};
            float vr[4] = {vv.x, vv.y, vv.z, vv.w};
#pragma unroll
            for (int i = 0; i < 4; i++)
#pragma unroll
                for (int j = 0; j < 4; j++)
                    acc[i][j] = fmaf(p[i], vr[j], acc[i][j]);
        }
    }

    // write O / l  -> y[b*T + q][h*64 + d]
    float inv[4];
#pragma unroll
    for (int i = 0; i < 4; i++) inv[i] = 1.0f / l_s[r0 + i];
#pragma unroll
    for (int i = 0; i < 4; i++) {
        float4 o;
        o.x = acc[i][0] * inv[i];
        o.y = acc[i][1] * inv[i];
        o.z = acc[i][2] * inv[i];
        o.w = acc[i][3] * inv[i];
        *(float4*)(y + (size_t)(b * 2048 + q0 + r0 + i) * 1024 + h * 64 + c0) = o;
    }
}

// ---------------- launch ---------------------------------------------------
static const int ATTN_SMEM = (4 * 64 * ALDS + 3 * 64) * (int)sizeof(float);

extern "C" void kernel_launch(void* const* d_in, const int* in_sizes, int n_in,
                              void* d_out, int out_size)
{
    const float* x      = (const float*)d_in[0];  // [4,2048,1024]
    const int*   l      = (const int*)  d_in[1];  // [4]
    const float* W_attn = (const float*)d_in[2];  // [1024,3072]
    const float* b_attn = (const float*)d_in[3];  // [3072]
    const float* W_proj = (const float*)d_in[4];  // [1024,1024]
    const float* b_proj = (const float*)d_in[5];  // [1024]
    float* out = (float*)d_out;                   // [4,2048,1024]

    float* qkv = nullptr;
    float* yb  = nullptr;
    cudaGetSymbolAddress((void**)&qkv, g_qkv);
    cudaGetSymbolAddress((void**)&yb,  g_y);

    cudaFuncSetAttribute(attn_kernel,
                         cudaFuncAttributeMaxDynamicSharedMemorySize, ATTN_SMEM);

    // 1) QKV = x @ W_attn + b_attn   (tf32 tensor cores)
    {
        dim3 grid(3072 / 128, 8192 / 128);
        sgemm_tf32_kernel<<<grid, 256>>>(x, W_attn, b_attn, qkv, 8192, 3072, 1024);
    }
    // 2) attention
    {
        dim3 grid(2048 / 64, 4 * 16);
        attn_kernel<<<grid, 256, ATTN_SMEM>>>(qkv, l, yb);
    }
    // 3) out = y @ W_proj + b_proj   (tf32 tensor cores)
    {
        dim3 grid(1024 / 128, 8192 / 128);
        sgemm_tf32_kernel<<<grid, 256>>>(yb, W_proj, b_proj, out, 8192, 1024, 1024);
    }
}

// round 4
// speedup vs baseline: 2.0896x; 1.4516x over previous
#include <cuda_runtime.h>
#include <math.h>

// ---------------- scratch (device globals: allocation-guard safe) ----------
__device__ float g_qkv[(size_t)8192 * 3072];   // [B*T, 3C]  Q|K|V packed per row
__device__ float g_y  [(size_t)8192 * 1024];   // [B*T, C]   attention output

// ---------------- tf32 helpers ---------------------------------------------
__device__ __forceinline__ unsigned f2tf(float f) {
    unsigned u;
    asm("cvt.rna.tf32.f32 %0, %1;" : "=r"(u) : "f"(f));
    return u;
}

#define MMA_TF32(d, av, bv)                                                   \
    asm volatile(                                                             \
        "mma.sync.aligned.m16n8k8.row.col.f32.tf32.tf32.f32 "                 \
        "{%0,%1,%2,%3},{%4,%5,%6,%7},{%8,%9},{%0,%1,%2,%3};"                  \
        : "+f"(d[0]), "+f"(d[1]), "+f"(d[2]), "+f"(d[3])                      \
        : "r"(av[0]), "r"(av[1]), "r"(av[2]), "r"(av[3]),                     \
          "r"(bv[0]), "r"(bv[1]))

// ---------------- tf32 SGEMM 128x128x16, 256 threads, tensor cores ---------
#define SA 132   // padded smem stride (floats)

__global__ void __launch_bounds__(256, 2) sgemm_tf32_kernel(
    const float* __restrict__ A,
    const float* __restrict__ B,
    const float* __restrict__ bias,
    float* __restrict__ C,
    int M, int N, int K)
{
    __shared__ unsigned AsU[2][16 * SA];   // [k][m] (tf32 bits)
    __shared__ unsigned BsU[2][16 * SA];   // [k][n] (tf32 bits)

    const int tid  = threadIdx.x;
    const int lane = tid & 31;
    const int wid  = tid >> 5;
    const int bx   = blockIdx.x;
    const int by   = blockIdx.y;

    const int warp_m = wid & 1;
    const int warp_n = wid >> 1;
    const int g  = lane >> 2;
    const int tg = lane & 3;

    const int amRow = tid >> 2;
    const int akc   = (tid & 3) << 2;
    const int bkr   = tid >> 5;
    const int bnc   = (tid & 31) << 2;

    const float* Ab = A + (size_t)(by * 128) * K;
    const float* Bb = B + bx * 128;

    float acc[4][4][4];
#pragma unroll
    for (int i = 0; i < 4; i++)
#pragma unroll
        for (int j = 0; j < 4; j++)
#pragma unroll
            for (int r = 0; r < 4; r++) acc[i][j][r] = 0.0f;

    float4 ra0 = *(const float4*)(Ab + (size_t)amRow * K + akc);
    float4 ra1 = *(const float4*)(Ab + (size_t)(amRow + 64) * K + akc);
    float4 rb0 = *(const float4*)(Bb + (size_t)bkr * N + bnc);
    float4 rb1 = *(const float4*)(Bb + (size_t)(bkr + 8) * N + bnc);
    {
        AsU[0][(akc + 0) * SA + amRow] = f2tf(ra0.x);
        AsU[0][(akc + 1) * SA + amRow] = f2tf(ra0.y);
        AsU[0][(akc + 2) * SA + amRow] = f2tf(ra0.z);
        AsU[0][(akc + 3) * SA + amRow] = f2tf(ra0.w);
        AsU[0][(akc + 0) * SA + amRow + 64] = f2tf(ra1.x);
        AsU[0][(akc + 1) * SA + amRow + 64] = f2tf(ra1.y);
        AsU[0][(akc + 2) * SA + amRow + 64] = f2tf(ra1.z);
        AsU[0][(akc + 3) * SA + amRow + 64] = f2tf(ra1.w);
        BsU[0][bkr * SA + bnc + 0] = f2tf(rb0.x);
        BsU[0][bkr * SA + bnc + 1] = f2tf(rb0.y);
        BsU[0][bkr * SA + bnc + 2] = f2tf(rb0.z);
        BsU[0][bkr * SA + bnc + 3] = f2tf(rb0.w);
        BsU[0][(bkr + 8) * SA + bnc + 0] = f2tf(rb1.x);
        BsU[0][(bkr + 8) * SA + bnc + 1] = f2tf(rb1.y);
        BsU[0][(bkr + 8) * SA + bnc + 2] = f2tf(rb1.z);
        BsU[0][(bkr + 8) * SA + bnc + 3] = f2tf(rb1.w);
    }
    __syncthreads();

    int buf = 0;
    for (int k0 = 0; k0 < K; k0 += 16) {
        const bool hasNext = (k0 + 16) < K;
        if (hasNext) {
            const float* An = Ab + k0 + 16;
            const float* Bn = Bb + (size_t)(k0 + 16) * N;
            ra0 = *(const float4*)(An + (size_t)amRow * K + akc);
            ra1 = *(const float4*)(An + (size_t)(amRow + 64) * K + akc);
            rb0 = *(const float4*)(Bn + (size_t)bkr * N + bnc);
            rb1 = *(const float4*)(Bn + (size_t)(bkr + 8) * N + bnc);
        }

        const unsigned* As = AsU[buf];
        const unsigned* Bs = BsU[buf];
#pragma unroll
        for (int ks = 0; ks < 16; ks += 8) {
            unsigned af[4][4], bf[4][2];
#pragma unroll
            for (int i = 0; i < 4; i++) {
                const int m = warp_m * 64 + i * 16 + g;
                af[i][0] = As[(ks + tg) * SA + m];
                af[i][1] = As[(ks + tg) * SA + m + 8];
                af[i][2] = As[(ks + tg + 4) * SA + m];
                af[i][3] = As[(ks + tg + 4) * SA + m + 8];
            }
#pragma unroll
            for (int j = 0; j < 4; j++) {
                const int n = warp_n * 32 + j * 8 + g;
                bf[j][0] = Bs[(ks + tg) * SA + n];
                bf[j][1] = Bs[(ks + tg + 4) * SA + n];
            }
#pragma unroll
            for (int i = 0; i < 4; i++)
#pragma unroll
                for (int j = 0; j < 4; j++)
                    MMA_TF32(acc[i][j], af[i], bf[j]);
        }

        if (hasNext) {
            const int nb = buf ^ 1;
            AsU[nb][(akc + 0) * SA + amRow] = f2tf(ra0.x);
            AsU[nb][(akc + 1) * SA + amRow] = f2tf(ra0.y);
            AsU[nb][(akc + 2) * SA + amRow] = f2tf(ra0.z);
            AsU[nb][(akc + 3) * SA + amRow] = f2tf(ra0.w);
            AsU[nb][(akc + 0) * SA + amRow + 64] = f2tf(ra1.x);
            AsU[nb][(akc + 1) * SA + amRow + 64] = f2tf(ra1.y);
            AsU[nb][(akc + 2) * SA + amRow + 64] = f2tf(ra1.z);
            AsU[nb][(akc + 3) * SA + amRow + 64] = f2tf(ra1.w);
            BsU[nb][bkr * SA + bnc + 0] = f2tf(rb0.x);
            BsU[nb][bkr * SA + bnc + 1] = f2tf(rb0.y);
            BsU[nb][bkr * SA + bnc + 2] = f2tf(rb0.z);
            BsU[nb][bkr * SA + bnc + 3] = f2tf(rb0.w);
            BsU[nb][(bkr + 8) * SA + bnc + 0] = f2tf(rb1.x);
            BsU[nb][(bkr + 8) * SA + bnc + 1] = f2tf(rb1.y);
            BsU[nb][(bkr + 8) * SA + bnc + 2] = f2tf(rb1.z);
            BsU[nb][(bkr + 8) * SA + bnc + 3] = f2tf(rb1.w);
        }
        __syncthreads();
        buf ^= 1;
    }

#pragma unroll
    for (int i = 0; i < 4; i++) {
        const int row = by * 128 + warp_m * 64 + i * 16 + g;
#pragma unroll
        for (int j = 0; j < 4; j++) {
            const int col = bx * 128 + warp_n * 32 + j * 8 + tg * 2;
            const float2 bv = *(const float2*)(bias + col);
            float2 o0, o1;
            o0.x = acc[i][j][0] + bv.x; o0.y = acc[i][j][1] + bv.y;
            o1.x = acc[i][j][2] + bv.x; o1.y = acc[i][j][3] + bv.y;
            *(float2*)(C + (size_t)row * N + col)       = o0;
            *(float2*)(C + (size_t)(row + 8) * N + col) = o1;
        }
    }
}

// ---------------- tensor-core flash attention ------------------------------
// 64q x 64k tiles, 8 warps; QK^T with 2-term tf32 split (fp32-grade logits),
// PV in plain tf32. Mask semantics preserved:
//   q <  l : causal; masked -> -1e30 sentinel (exp underflows to 0)
//   q >= l : all keys, logit = s*0.125 + (-1e8f) in fp32 (reference-identical
//            quantization: all logits collapse to exactly -1e8 -> uniform)
#define LQK 68   // stride for Qh/Ql/Kh/Kl/Sp (conflict-free frag loads)
#define LV  72   // stride for V plane (conflict-free B-frag loads)

__global__ void __launch_bounds__(256, 2) attn_tc_kernel(
    const float* __restrict__ qkv,  // [B*T, 3072]; Q at col h*64, K +1024, V +2048
    const int*   __restrict__ lv,   // [B]
    float* __restrict__ y)          // [B*T, 1024]
{
    extern __shared__ float sm[];
    unsigned* Qh = (unsigned*)sm;          // [64][LQK]
    unsigned* Ql = Qh + 64 * LQK;
    unsigned* Kh = Ql + 64 * LQK;
    unsigned* Kl = Kh + 64 * LQK;
    unsigned* Vt = Kl + 64 * LQK;          // [64][LV] tf32
    float*    Sp = (float*)(Vt + 64 * LV); // [64][LQK] S then P(tf32 bits)
    float*    m_s = Sp + 64 * LQK;         // [64]
    float*    l_s = m_s + 64;
    float*    a_s = l_s + 64;

    const int tid  = threadIdx.x;
    const int lane = tid & 31;
    const int wid  = tid >> 5;
    const int g    = lane >> 2;
    const int tg   = lane & 3;
    const int wm   = wid >> 1;   // 0..3: 16-row slab of S/O
    const int wn   = wid & 1;    // 0..1: 32-col slab

    const int bh = blockIdx.y;
    const int b  = bh >> 4;
    const int h  = bh & 15;
    const int q0 = blockIdx.x * 64;
    const int lb = lv[b];

    const float* Qb = qkv + (size_t)b * 2048 * 3072 + h * 64;
    const float* Kb = Qb + 1024;
    const float* Vb = Qb + 2048;

    // ---- load Q tile (hi/lo split)
    for (int i = tid; i < 64 * 16; i += 256) {
        int r  = i >> 4;
        int d4 = (i & 15) << 2;
        float4 v = *(const float4*)(Qb + (size_t)(q0 + r) * 3072 + d4);
        float vv[4] = {v.x, v.y, v.z, v.w};
#pragma unroll
        for (int c = 0; c < 4; c++) {
            unsigned hb = f2tf(vv[c]);
            Qh[r * LQK + d4 + c] = hb;
            Ql[r * LQK + d4 + c] = f2tf(vv[c] - __uint_as_float(hb));
        }
    }
    if (tid < 64) { m_s[tid] = -1e30f; l_s[tid] = 0.0f; }

    float oacc[4][4];
#pragma unroll
    for (int j = 0; j < 4; j++)
#pragma unroll
        for (int r = 0; r < 4; r++) oacc[j][r] = 0.0f;

    const int ra   = wm * 16 + g;        // local S/O row (and +8)
    const int nTiles = (q0 + 64 <= lb) ? (blockIdx.x + 1) : 32;

    for (int t = 0; t < nTiles; t++) {
        const int k0 = t * 64;
        __syncthreads();   // prev PV (reads Sp,Vt) done; Q ready on iter 0

        // ---- load K (hi/lo) and V (tf32) tiles
        for (int i = tid; i < 64 * 16; i += 256) {
            int r  = i >> 4;
            int d4 = (i & 15) << 2;
            float4 kv = *(const float4*)(Kb + (size_t)(k0 + r) * 3072 + d4);
            float kk[4] = {kv.x, kv.y, kv.z, kv.w};
#pragma unroll
            for (int c = 0; c < 4; c++) {
                unsigned hb = f2tf(kk[c]);
                Kh[r * LQK + d4 + c] = hb;
                Kl[r * LQK + d4 + c] = f2tf(kk[c] - __uint_as_float(hb));
            }
            float4 vv = *(const float4*)(Vb + (size_t)(k0 + r) * 3072 + d4);
            Vt[r * LV + d4 + 0] = f2tf(vv.x);
            Vt[r * LV + d4 + 1] = f2tf(vv.y);
            Vt[r * LV + d4 + 2] = f2tf(vv.z);
            Vt[r * LV + d4 + 3] = f2tf(vv.w);
        }
        __syncthreads();

        // ---- S = Q K^T  (split tf32: hh + hl + lh)
        float sacc[4][4];
#pragma unroll
        for (int j = 0; j < 4; j++)
#pragma unroll
            for (int r = 0; r < 4; r++) sacc[j][r] = 0.0f;

#pragma unroll
        for (int kd = 0; kd < 64; kd += 8) {
            unsigned ah[4], alo[4];
            ah[0]  = Qh[ra * LQK + kd + tg];
            ah[1]  = Qh[(ra + 8) * LQK + kd + tg];
            ah[2]  = Qh[ra * LQK + kd + tg + 4];
            ah[3]  = Qh[(ra + 8) * LQK + kd + tg + 4];
            alo[0] = Ql[ra * LQK + kd + tg];
            alo[1] = Ql[(ra + 8) * LQK + kd + tg];
            alo[2] = Ql[ra * LQK + kd + tg + 4];
            alo[3] = Ql[(ra + 8) * LQK + kd + tg + 4];
#pragma unroll
            for (int j = 0; j < 4; j++) {
                const int cb = wn * 32 + j * 8 + g;
                unsigned bh_[2], bl_[2];
                bh_[0] = Kh[cb * LQK + kd + tg];
                bh_[1] = Kh[cb * LQK + kd + tg + 4];
                bl_[0] = Kl[cb * LQK + kd + tg];
                bl_[1] = Kl[cb * LQK + kd + tg + 4];
                MMA_TF32(sacc[j], ah, bh_);
                MMA_TF32(sacc[j], ah, bl_);
                MMA_TF32(sacc[j], alo, bh_);
            }
        }

        // ---- mask + store S to smem (fp32)
        const int qg0 = q0 + ra;
        const int qg1 = qg0 + 8;
#pragma unroll
        for (int j = 0; j < 4; j++) {
            const int kc = k0 + wn * 32 + j * 8 + 2 * tg;
            float v0 = sacc[j][0] * 0.125f;
            float v1 = sacc[j][1] * 0.125f;
            float v2 = sacc[j][2] * 0.125f;
            float v3 = sacc[j][3] * 0.125f;
            if (qg0 < lb) {
                if (kc > qg0)     v0 = -1e30f;
                if (kc + 1 > qg0) v1 = -1e30f;
            } else { v0 += -1e8f; v1 += -1e8f; }
            if (qg1 < lb) {
                if (kc > qg1)     v2 = -1e30f;
                if (kc + 1 > qg1) v3 = -1e30f;
            } else { v2 += -1e8f; v3 += -1e8f; }
            const int cl = wn * 32 + j * 8 + 2 * tg;
            Sp[ra * LQK + cl]           = v0;
            Sp[ra * LQK + cl + 1]       = v1;
            Sp[(ra + 8) * LQK + cl]     = v2;
            Sp[(ra + 8) * LQK + cl + 1] = v3;
        }
        __syncthreads();

        // ---- online softmax: 4 threads per row, 16 cols each
        {
            const int r   = tid >> 2;
            const int sub = tid & 3;
            float* row = Sp + r * LQK + sub * 16;
            float mx = -1e30f;
#pragma unroll
            for (int c = 0; c < 16; c++) mx = fmaxf(mx, row[c]);
            mx = fmaxf(mx, __shfl_xor_sync(0xffffffffu, mx, 1));
            mx = fmaxf(mx, __shfl_xor_sync(0xffffffffu, mx, 2));
            const float m_old = m_s[r];
            const float m_new = fmaxf(m_old, mx);
            float sum = 0.0f;
#pragma unroll
            for (int c = 0; c < 16; c++) {
                float e = __expf(row[c] - m_new);
                sum += e;
                ((unsigned*)row)[c] = f2tf(e);   // P as tf32 bits
            }
            sum += __shfl_xor_sync(0xffffffffu, sum, 1);
            sum += __shfl_xor_sync(0xffffffffu, sum, 2);
            if (sub == 0) {
                const float alpha = __expf(m_old - m_new);
                l_s[r] = l_s[r] * alpha + sum;
                m_s[r] = m_new;
                a_s[r] = alpha;
            }
        }
        __syncthreads();

        // ---- O = O*alpha + P V
        const float al0 = a_s[ra];
        const float al1 = a_s[ra + 8];
#pragma unroll
        for (int j = 0; j < 4; j++) {
            oacc[j][0] *= al0; oacc[j][1] *= al0;
            oacc[j][2] *= al1; oacc[j][3] *= al1;
        }
        const unsigned* Pu = (const unsigned*)Sp;
#pragma unroll
        for (int kc = 0; kc < 64; kc += 8) {
            unsigned pa[4];
            pa[0] = Pu[ra * LQK + kc + tg];
            pa[1] = Pu[(ra + 8) * LQK + kc + tg];
            pa[2] = Pu[ra * LQK + kc + tg + 4];
            pa[3] = Pu[(ra + 8) * LQK + kc + tg + 4];
#pragma unroll
            for (int j = 0; j < 4; j++) {
                const int db = wn * 32 + j * 8 + g;
                unsigned bv[2];
                bv[0] = Vt[(kc + tg) * LV + db];
                bv[1] = Vt[(kc + tg + 4) * LV + db];
                MMA_TF32(oacc[j], pa, bv);
            }
        }
    }

    // ---- normalize + store
    const float inv0 = 1.0f / l_s[ra];
    const float inv1 = 1.0f / l_s[ra + 8];
    float* yr0 = y + (size_t)(b * 2048 + q0 + ra) * 1024 + h * 64;
    float* yr1 = y + (size_t)(b * 2048 + q0 + ra + 8) * 1024 + h * 64;
#pragma unroll
    for (int j = 0; j < 4; j++) {
        const int cl = wn * 32 + j * 8 + 2 * tg;
        float2 o0, o1;
        o0.x = oacc[j][0] * inv0; o0.y = oacc[j][1] * inv0;
        o1.x = oacc[j][2] * inv1; o1.y = oacc[j][3] * inv1;
        *(float2*)(yr0 + cl) = o0;
        *(float2*)(yr1 + cl) = o1;
    }
}

// ---------------- launch ---------------------------------------------------
static const int ATTN_SMEM =
    (4 * 64 * LQK + 64 * LV + 64 * LQK + 3 * 64) * (int)sizeof(float);

extern "C" void kernel_launch(void* const* d_in, const int* in_sizes, int n_in,
                              void* d_out, int out_size)
{
    const float* x      = (const float*)d_in[0];
    const int*   l      = (const int*)  d_in[1];
    const float* W_attn = (const float*)d_in[2];
    const float* b_attn = (const float*)d_in[3];
    const float* W_proj = (const float*)d_in[4];
    const float* b_proj = (const float*)d_in[5];
    float* out = (float*)d_out;

    float* qkv = nullptr;
    float* yb  = nullptr;
    cudaGetSymbolAddress((void**)&qkv, g_qkv);
    cudaGetSymbolAddress((void**)&yb,  g_y);

    cudaFuncSetAttribute(attn_tc_kernel,
                         cudaFuncAttributeMaxDynamicSharedMemorySize, ATTN_SMEM);

    // 1) QKV = x @ W_attn + b_attn   (tf32 tensor cores)
    {
        dim3 grid(3072 / 128, 8192 / 128);
        sgemm_tf32_kernel<<<grid, 256>>>(x, W_attn, b_attn, qkv, 8192, 3072, 1024);
    }
    // 2) attention (tensor cores, split-tf32 QK)
    {
        dim3 grid(2048 / 64, 4 * 16);
        attn_tc_kernel<<<grid, 256, ATTN_SMEM>>>(qkv, l, yb);
    }
    // 3) out = y @ W_proj + b_proj   (tf32 tensor cores)
    {
        dim3 grid(1024 / 128, 8192 / 128);
        sgemm_tf32_kernel<<<grid, 256>>>(yb, W_proj, b_proj, out, 8192, 1024, 1024);
    }
}

// round 6
// speedup vs baseline: 3.2638x; 1.5619x over previous
#include <cuda_runtime.h>
#include <math.h>

// ---------------- scratch (device globals: allocation-guard safe) ----------
__device__ float g_qkv[(size_t)8192 * 3072];   // [B*T, 3C]  Q|K|V packed per row
__device__ float g_y  [(size_t)8192 * 1024];   // [B*T, C]   attention output

// ---------------- tf32 helpers ---------------------------------------------
__device__ __forceinline__ unsigned f2tf(float f) {
    unsigned u;
    asm("cvt.rna.tf32.f32 %0, %1;" : "=r"(u) : "f"(f));
    return u;
}

#define MMA_TF32(d, av, bv)                                                   \
    asm volatile(                                                             \
        "mma.sync.aligned.m16n8k8.row.col.f32.tf32.tf32.f32 "                 \
        "{%0,%1,%2,%3},{%4,%5,%6,%7},{%8,%9},{%0,%1,%2,%3};"                  \
        : "+f"(d[0]), "+f"(d[1]), "+f"(d[2]), "+f"(d[3])                      \
        : "r"(av[0]), "r"(av[1]), "r"(av[2]), "r"(av[3]),                     \
          "r"(bv[0]), "r"(bv[1]))

// ---------------- tf32 SGEMM 128x128x16, 256 threads, tensor cores ---------
#define SA 132   // padded smem stride (floats)

__global__ void __launch_bounds__(256, 2) sgemm_tf32_kernel(
    const float* __restrict__ A,
    const float* __restrict__ B,
    const float* __restrict__ bias,
    float* __restrict__ C,
    int M, int N, int K)
{
    __shared__ unsigned AsU[2][16 * SA];   // [k][m] (tf32 bits)
    __shared__ unsigned BsU[2][16 * SA];   // [k][n] (tf32 bits)

    const int tid  = threadIdx.x;
    const int lane = tid & 31;
    const int wid  = tid >> 5;
    const int bx   = blockIdx.x;
    const int by   = blockIdx.y;

    const int warp_m = wid & 1;
    const int warp_n = wid >> 1;
    const int g  = lane >> 2;
    const int tg = lane & 3;

    const int amRow = tid >> 2;
    const int akc   = (tid & 3) << 2;
    const int bkr   = tid >> 5;
    const int bnc   = (tid & 31) << 2;

    const float* Ab = A + (size_t)(by * 128) * K;
    const float* Bb = B + bx * 128;

    float acc[4][4][4];
#pragma unroll
    for (int i = 0; i < 4; i++)
#pragma unroll
        for (int j = 0; j < 4; j++)
#pragma unroll
            for (int r = 0; r < 4; r++) acc[i][j][r] = 0.0f;

    float4 ra0 = *(const float4*)(Ab + (size_t)amRow * K + akc);
    float4 ra1 = *(const float4*)(Ab + (size_t)(amRow + 64) * K + akc);
    float4 rb0 = *(const float4*)(Bb + (size_t)bkr * N + bnc);
    float4 rb1 = *(const float4*)(Bb + (size_t)(bkr + 8) * N + bnc);
    {
        AsU[0][(akc + 0) * SA + amRow] = f2tf(ra0.x);
        AsU[0][(akc + 1) * SA + amRow] = f2tf(ra0.y);
        AsU[0][(akc + 2) * SA + amRow] = f2tf(ra0.z);
        AsU[0][(akc + 3) * SA + amRow] = f2tf(ra0.w);
        AsU[0][(akc + 0) * SA + amRow + 64] = f2tf(ra1.x);
        AsU[0][(akc + 1) * SA + amRow + 64] = f2tf(ra1.y);
        AsU[0][(akc + 2) * SA + amRow + 64] = f2tf(ra1.z);
        AsU[0][(akc + 3) * SA + amRow + 64] = f2tf(ra1.w);
        BsU[0][bkr * SA + bnc + 0] = f2tf(rb0.x);
        BsU[0][bkr * SA + bnc + 1] = f2tf(rb0.y);
        BsU[0][bkr * SA + bnc + 2] = f2tf(rb0.z);
        BsU[0][bkr * SA + bnc + 3] = f2tf(rb0.w);
        BsU[0][(bkr + 8) * SA + bnc + 0] = f2tf(rb1.x);
        BsU[0][(bkr + 8) * SA + bnc + 1] = f2tf(rb1.y);
        BsU[0][(bkr + 8) * SA + bnc + 2] = f2tf(rb1.z);
        BsU[0][(bkr + 8) * SA + bnc + 3] = f2tf(rb1.w);
    }
    __syncthreads();

    int buf = 0;
    for (int k0 = 0; k0 < K; k0 += 16) {
        const bool hasNext = (k0 + 16) < K;
        if (hasNext) {
            const float* An = Ab + k0 + 16;
            const float* Bn = Bb + (size_t)(k0 + 16) * N;
            ra0 = *(const float4*)(An + (size_t)amRow * K + akc);
            ra1 = *(const float4*)(An + (size_t)(amRow + 64) * K + akc);
            rb0 = *(const float4*)(Bn + (size_t)bkr * N + bnc);
            rb1 = *(const float4*)(Bn + (size_t)(bkr + 8) * N + bnc);
        }

        const unsigned* As = AsU[buf];
        const unsigned* Bs = BsU[buf];
#pragma unroll
        for (int ks = 0; ks < 16; ks += 8) {
            unsigned af[4][4], bf[4][2];
#pragma unroll
            for (int i = 0; i < 4; i++) {
                const int m = warp_m * 64 + i * 16 + g;
                af[i][0] = As[(ks + tg) * SA + m];
                af[i][1] = As[(ks + tg) * SA + m + 8];
                af[i][2] = As[(ks + tg + 4) * SA + m];
                af[i][3] = As[(ks + tg + 4) * SA + m + 8];
            }
#pragma unroll
            for (int j = 0; j < 4; j++) {
                const int n = warp_n * 32 + j * 8 + g;
                bf[j][0] = Bs[(ks + tg) * SA + n];
                bf[j][1] = Bs[(ks + tg + 4) * SA + n];
            }
#pragma unroll
            for (int i = 0; i < 4; i++)
#pragma unroll
                for (int j = 0; j < 4; j++)
                    MMA_TF32(acc[i][j], af[i], bf[j]);
        }

        if (hasNext) {
            const int nb = buf ^ 1;
            AsU[nb][(akc + 0) * SA + amRow] = f2tf(ra0.x);
            AsU[nb][(akc + 1) * SA + amRow] = f2tf(ra0.y);
            AsU[nb][(akc + 2) * SA + amRow] = f2tf(ra0.z);
            AsU[nb][(akc + 3) * SA + amRow] = f2tf(ra0.w);
            AsU[nb][(akc + 0) * SA + amRow + 64] = f2tf(ra1.x);
            AsU[nb][(akc + 1) * SA + amRow + 64] = f2tf(ra1.y);
            AsU[nb][(akc + 2) * SA + amRow + 64] = f2tf(ra1.z);
            AsU[nb][(akc + 3) * SA + amRow + 64] = f2tf(ra1.w);
            BsU[nb][bkr * SA + bnc + 0] = f2tf(rb0.x);
            BsU[nb][bkr * SA + bnc + 1] = f2tf(rb0.y);
            BsU[nb][bkr * SA + bnc + 2] = f2tf(rb0.z);
            BsU[nb][bkr * SA + bnc + 3] = f2tf(rb0.w);
            BsU[nb][(bkr + 8) * SA + bnc + 0] = f2tf(rb1.x);
            BsU[nb][(bkr + 8) * SA + bnc + 1] = f2tf(rb1.y);
            BsU[nb][(bkr + 8) * SA + bnc + 2] = f2tf(rb1.z);
            BsU[nb][(bkr + 8) * SA + bnc + 3] = f2tf(rb1.w);
        }
        __syncthreads();
        buf ^= 1;
    }

#pragma unroll
    for (int i = 0; i < 4; i++) {
        const int row = by * 128 + warp_m * 64 + i * 16 + g;
#pragma unroll
        for (int j = 0; j < 4; j++) {
            const int col = bx * 128 + warp_n * 32 + j * 8 + tg * 2;
            const float2 bv = *(const float2*)(bias + col);
            float2 o0, o1;
            o0.x = acc[i][j][0] + bv.x; o0.y = acc[i][j][1] + bv.y;
            o1.x = acc[i][j][2] + bv.x; o1.y = acc[i][j][3] + bv.y;
            *(float2*)(C + (size_t)row * N + col)       = o0;
            *(float2*)(C + (size_t)(row + 8) * N + col) = o1;
        }
    }
}

// ---------------- masked-row mean kernel ------------------------------------
// For rows q >= l[b], the reference's additive -1e8 mask quantizes every
// logit to exactly -1e8 in fp32 (|s/8| << 4 = half-ulp at 1e8), so softmax is
// exactly uniform and y_row = mean(V) over all T keys — identical for all
// masked rows of a (b,h). Compute it once and broadcast.
__global__ void __launch_bounds__(256) vmean_kernel(
    const float* __restrict__ qkv, const int* __restrict__ lv,
    float* __restrict__ y)
{
    const int b  = blockIdx.x >> 4;
    const int h  = blockIdx.x & 15;
    const int lb = lv[b];
    __shared__ float part[4][64];

    const int d = threadIdx.x & 63;
    const int c = threadIdx.x >> 6;
    const float* Vb = qkv + (size_t)b * 2048 * 3072 + 2048 + h * 64 + d;

    float s = 0.0f;
    const float* p = Vb + (size_t)(c * 512) * 3072;
#pragma unroll 8
    for (int t = 0; t < 512; t++) s += p[(size_t)t * 3072];
    part[c][d] = s;
    __syncthreads();

    if (threadIdx.x < 64) {
        part[0][d] = (part[0][d] + part[1][d] + part[2][d] + part[3][d])
                   * (1.0f / 2048.0f);
    }
    __syncthreads();

    const float m = part[0][d];
    for (int t = lb + c; t < 2048; t += 4)
        y[(size_t)(b * 2048 + t) * 1024 + h * 64 + d] = m;
}

// ---------------- tensor-core flash attention (causal rows only) -----------
// Rows q >= l[b] are produced by vmean_kernel; blocks fully above l exit,
// straddle blocks run causal tiles and store only rows q < l.
#define LQK 68
#define LV  72

__global__ void __launch_bounds__(256, 2) attn_tc_kernel(
    const float* __restrict__ qkv,
    const int*   __restrict__ lv,
    float* __restrict__ y)
{
    extern __shared__ float sm[];
    unsigned* Qh = (unsigned*)sm;
    unsigned* Ql = Qh + 64 * LQK;
    unsigned* Kh = Ql + 64 * LQK;
    unsigned* Kl = Kh + 64 * LQK;
    unsigned* Vt = Kl + 64 * LQK;
    float*    Sp = (float*)(Vt + 64 * LV);
    float*    m_s = Sp + 64 * LQK;
    float*    l_s = m_s + 64;
    float*    a_s = l_s + 64;

    const int tid  = threadIdx.x;
    const int lane = tid & 31;
    const int wid  = tid >> 5;
    const int g    = lane >> 2;
    const int tg   = lane & 3;
    const int wm   = wid >> 1;
    const int wn   = wid & 1;

    const int bh = blockIdx.y;
    const int b  = bh >> 4;
    const int h  = bh & 15;
    const int q0 = blockIdx.x * 64;
    const int lb = lv[b];

    if (q0 >= lb) return;   // all rows masked -> handled by vmean_kernel

    const float* Qb = qkv + (size_t)b * 2048 * 3072 + h * 64;
    const float* Kb = Qb + 1024;
    const float* Vb = Qb + 2048;

    for (int i = tid; i < 64 * 16; i += 256) {
        int r  = i >> 4;
        int d4 = (i & 15) << 2;
        float4 v = *(const float4*)(Qb + (size_t)(q0 + r) * 3072 + d4);
        float vv[4] = {v.x, v.y, v.z, v.w};
#pragma unroll
        for (int c = 0; c < 4; c++) {
            unsigned hb = f2tf(vv[c]);
            Qh[r * LQK + d4 + c] = hb;
            Ql[r * LQK + d4 + c] = f2tf(vv[c] - __uint_as_float(hb));
        }
    }
    if (tid < 64) { m_s[tid] = -1e30f; l_s[tid] = 0.0f; }

    float oacc[4][4];
#pragma unroll
    for (int j = 0; j < 4; j++)
#pragma unroll
        for (int r = 0; r < 4; r++) oacc[j][r] = 0.0f;

    const int ra = wm * 16 + g;
    const int nTiles = blockIdx.x + 1;   // causal only

    for (int t = 0; t < nTiles; t++) {
        const int k0 = t * 64;
        __syncthreads();

        for (int i = tid; i < 64 * 16; i += 256) {
            int r  = i >> 4;
            int d4 = (i & 15) << 2;
            float4 kv = *(const float4*)(Kb + (size_t)(k0 + r) * 3072 + d4);
            float kk[4] = {kv.x, kv.y, kv.z, kv.w};
#pragma unroll
            for (int c = 0; c < 4; c++) {
                unsigned hb = f2tf(kk[c]);
                Kh[r * LQK + d4 + c] = hb;
                Kl[r * LQK + d4 + c] = f2tf(kk[c] - __uint_as_float(hb));
            }
            float4 vv = *(const float4*)(Vb + (size_t)(k0 + r) * 3072 + d4);
            Vt[r * LV + d4 + 0] = f2tf(vv.x);
            Vt[r * LV + d4 + 1] = f2tf(vv.y);
            Vt[r * LV + d4 + 2] = f2tf(vv.z);
            Vt[r * LV + d4 + 3] = f2tf(vv.w);
        }
        __syncthreads();

        float sacc[4][4];
#pragma unroll
        for (int j = 0; j < 4; j++)
#pragma unroll
            for (int r = 0; r < 4; r++) sacc[j][r] = 0.0f;

#pragma unroll
        for (int kd = 0; kd < 64; kd += 8) {
            unsigned ah[4], alo[4];
            ah[0]  = Qh[ra * LQK + kd + tg];
            ah[1]  = Qh[(ra + 8) * LQK + kd + tg];
            ah[2]  = Qh[ra * LQK + kd + tg + 4];
            ah[3]  = Qh[(ra + 8) * LQK + kd + tg + 4];
            alo[0] = Ql[ra * LQK + kd + tg];
            alo[1] = Ql[(ra + 8) * LQK + kd + tg];
            alo[2] = Ql[ra * LQK + kd + tg + 4];
            alo[3] = Ql[(ra + 8) * LQK + kd + tg + 4];
#pragma unroll
            for (int j = 0; j < 4; j++) {
                const int cb = wn * 32 + j * 8 + g;
                unsigned bh_[2], bl_[2];
                bh_[0] = Kh[cb * LQK + kd + tg];
                bh_[1] = Kh[cb * LQK + kd + tg + 4];
                bl_[0] = Kl[cb * LQK + kd + tg];
                bl_[1] = Kl[cb * LQK + kd + tg + 4];
                MMA_TF32(sacc[j], ah, bh_);
                MMA_TF32(sacc[j], ah, bl_);
                MMA_TF32(sacc[j], alo, bh_);
            }
        }

        const int qg0 = q0 + ra;
        const int qg1 = qg0 + 8;
#pragma unroll
        for (int j = 0; j < 4; j++) {
            const int kc = k0 + wn * 32 + j * 8 + 2 * tg;
            float v0 = sacc[j][0] * 0.125f;
            float v1 = sacc[j][1] * 0.125f;
            float v2 = sacc[j][2] * 0.125f;
            float v3 = sacc[j][3] * 0.125f;
            if (qg0 < lb) {
                if (kc > qg0)     v0 = -1e30f;
                if (kc + 1 > qg0) v1 = -1e30f;
            } else { v0 += -1e8f; v1 += -1e8f; }
            if (qg1 < lb) {
                if (kc > qg1)     v2 = -1e30f;
                if (kc + 1 > qg1) v3 = -1e30f;
            } else { v2 += -1e8f; v3 += -1e8f; }
            const int cl = wn * 32 + j * 8 + 2 * tg;
            Sp[ra * LQK + cl]           = v0;
            Sp[ra * LQK + cl + 1]       = v1;
            Sp[(ra + 8) * LQK + cl]     = v2;
            Sp[(ra + 8) * LQK + cl + 1] = v3;
        }
        __syncthreads();

        {
            const int r   = tid >> 2;
            const int sub = tid & 3;
            float* row = Sp + r * LQK + sub * 16;
            float mx = -1e30f;
#pragma unroll
            for (int c = 0; c < 16; c++) mx = fmaxf(mx, row[c]);
            mx = fmaxf(mx, __shfl_xor_sync(0xffffffffu, mx, 1));
            mx = fmaxf(mx, __shfl_xor_sync(0xffffffffu, mx, 2));
            const float m_old = m_s[r];
            const float m_new = fmaxf(m_old, mx);
            float sum = 0.0f;
#pragma unroll
            for (int c = 0; c < 16; c++) {
                float e = __expf(row[c] - m_new);
                sum += e;
                ((unsigned*)row)[c] = f2tf(e);
            }
            sum += __shfl_xor_sync(0xffffffffu, sum, 1);
            sum += __shfl_xor_sync(0xffffffffu, sum, 2);
            if (sub == 0) {
                const float alpha = __expf(m_old - m_new);
                l_s[r] = l_s[r] * alpha + sum;
                m_s[r] = m_new;
                a_s[r] = alpha;
            }
        }
        __syncthreads();

        const float al0 = a_s[ra];
        const float al1 = a_s[ra + 8];
#pragma unroll
        for (int j = 0; j < 4; j++) {
            oacc[j][0] *= al0; oacc[j][1] *= al0;
            oacc[j][2] *= al1; oacc[j][3] *= al1;
        }
        const unsigned* Pu = (const unsigned*)Sp;
#pragma unroll
        for (int kc = 0; kc < 64; kc += 8) {
            unsigned pa[4];
            pa[0] = Pu[ra * LQK + kc + tg];
            pa[1] = Pu[(ra + 8) * LQK + kc + tg];
            pa[2] = Pu[ra * LQK + kc + tg + 4];
            pa[3] = Pu[(ra + 8) * LQK + kc + tg + 4];
#pragma unroll
            for (int j = 0; j < 4; j++) {
                const int db = wn * 32 + j * 8 + g;
                unsigned bv[2];
                bv[0] = Vt[(kc + tg) * LV + db];
                bv[1] = Vt[(kc + tg + 4) * LV + db];
                MMA_TF32(oacc[j], pa, bv);
            }
        }
    }

    // store only rows q < lb (masked rows owned by vmean_kernel)
    const float inv0 = 1.0f / l_s[ra];
    const float inv1 = 1.0f / l_s[ra + 8];
    float* yr0 = y + (size_t)(b * 2048 + q0 + ra) * 1024 + h * 64;
    float* yr1 = y + (size_t)(b * 2048 + q0 + ra + 8) * 1024 + h * 64;
    const bool st0 = (q0 + ra)     < lb;
    const bool st1 = (q0 + ra + 8) < lb;
#pragma unroll
    for (int j = 0; j < 4; j++) {
        const int cl = wn * 32 + j * 8 + 2 * tg;
        if (st0) {
            float2 o0;
            o0.x = oacc[j][0] * inv0; o0.y = oacc[j][1] * inv0;
            *(float2*)(yr0 + cl) = o0;
        }
        if (st1) {
            float2 o1;
            o1.x = oacc[j][2] * inv1; o1.y = oacc[j][3] * inv1;
            *(float2*)(yr1 + cl) = o1;
        }
    }
}

// ---------------- launch ---------------------------------------------------
static const int ATTN_SMEM =
    (4 * 64 * LQK + 64 * LV + 64 * LQK + 3 * 64) * (int)sizeof(float);

extern "C" void kernel_launch(void* const* d_in, const int* in_sizes, int n_in,
                              void* d_out, int out_size)
{
    const float* x      = (const float*)d_in[0];
    const int*   l      = (const int*)  d_in[1];
    const float* W_attn = (const float*)d_in[2];
    const float* b_attn = (const float*)d_in[3];
    const float* W_proj = (const float*)d_in[4];
    const float* b_proj = (const float*)d_in[5];
    float* out = (float*)d_out;

    float* qkv = nullptr;
    float* yb  = nullptr;
    cudaGetSymbolAddress((void**)&qkv, g_qkv);
    cudaGetSymbolAddress((void**)&yb,  g_y);

    cudaFuncSetAttribute(attn_tc_kernel,
                         cudaFuncAttributeMaxDynamicSharedMemorySize, ATTN_SMEM);

    // 1) QKV = x @ W_attn + b_attn   (tf32 tensor cores)
    {
        dim3 grid(3072 / 128, 8192 / 128);
        sgemm_tf32_kernel<<<grid, 256>>>(x, W_attn, b_attn, qkv, 8192, 3072, 1024);
    }
    // 2a) masked-row means (rows q >= l)
    vmean_kernel<<<64, 256>>>(qkv, l, yb);
    // 2b) attention, causal rows only
    {
        dim3 grid(2048 / 64, 4 * 16);
        attn_tc_kernel<<<grid, 256, ATTN_SMEM>>>(qkv, l, yb);
    }
    // 3) out = y @ W_proj + b_proj   (tf32 tensor cores)
    {
        dim3 grid(1024 / 128, 8192 / 128);
        sgemm_tf32_kernel<<<grid, 256>>>(yb, W_proj, b_proj, out, 8192, 1024, 1024);
    }
}

// round 7
// speedup vs baseline: 3.5002x; 1.0725x over previous
#include <cuda_runtime.h>
#include <math.h>

// ---------------- scratch (device globals: allocation-guard safe) ----------
__device__ float g_qkv[(size_t)8192 * 3072];   // [B*T, 3C]  Q|K|V packed per row
__device__ float g_y  [(size_t)8192 * 1024];   // [B*T, C]   attention output

// ---------------- tf32 helpers ---------------------------------------------
__device__ __forceinline__ unsigned f2tf(float f) {
    unsigned u;
    asm("cvt.rna.tf32.f32 %0, %1;" : "=r"(u) : "f"(f));
    return u;
}

#define MMA_TF32(d, av, bv)                                                   \
    asm volatile(                                                             \
        "mma.sync.aligned.m16n8k8.row.col.f32.tf32.tf32.f32 "                 \
        "{%0,%1,%2,%3},{%4,%5,%6,%7},{%8,%9},{%0,%1,%2,%3};"                  \
        : "+f"(d[0]), "+f"(d[1]), "+f"(d[2]), "+f"(d[3])                      \
        : "r"(av[0]), "r"(av[1]), "r"(av[2]), "r"(av[3]),                     \
          "r"(bv[0]), "r"(bv[1]))

// ---------------- tf32 SGEMM, fragment-packed smem -------------------------
// 128x128x16 tiles, 256 threads, 8 warps (warp tile 64x32).
// Smem holds A/B ALREADY in mma fragment layout:
//   A block (32 lanes x 4 regs): reg r = mhalf + 2*khalf, lane = 4*(m&7)+(k&3)
//     block id = (m>>6)*8 + ((m>>4)&3)*2 + (k>>3)
//   B block: reg r = khalf + 2*jodd (two n8-tiles packed), lane = 4*(n&7)+(k&3)
//     block id = (n>>5)*4 + ((n>>4)&1)*2 + (k>>3)
// Mainloop fragment fetch = LDS.128 (4 for A, 2 for B per k8 slice).
#define NBLK 132   // floats per block (128 + 4 pad; 528B = 33*16 keeps alignment)

__global__ void __launch_bounds__(256, 2) sgemm_tf32_kernel(
    const float* __restrict__ A,
    const float* __restrict__ B,
    const float* __restrict__ bias,
    float* __restrict__ C,
    int M, int N, int K)
{
    __shared__ unsigned Abuf[2][16 * NBLK];
    __shared__ unsigned Bbuf[2][16 * NBLK];

    const int tid  = threadIdx.x;
    const int lane = tid & 31;
    const int wid  = tid >> 5;
    const int bx   = blockIdx.x;
    const int by   = blockIdx.y;

    const int wm = wid & 1;     // 64-row slab
    const int wn = wid >> 1;    // 32-col slab
    const int g  = lane >> 2;
    const int tg = lane & 3;

    // ---- staging index maps
    // A: thread -> row aRow (0..127), k half aK0 (0 or 8); 8 floats/chunk
    const int aRow = tid >> 1;
    const int aK0  = (tid & 1) << 3;
    const int aBlk = ((aRow >> 6) << 3) + (((aRow >> 4) & 3) << 1) + (aK0 >> 3);
    const int aPosB = ((aRow & 7) << 4) + ((aRow >> 3) & 1);
    // B: thread -> k row kr (0..15), col group nc (0..120); 8 floats/chunk
    const int kr = tid >> 4;
    const int nc = (tid & 15) << 3;
    const int bBlk = ((nc >> 5) << 2) + (((nc >> 4) & 1) << 1) + ((kr >> 3) & 1);
    const int bPosB = 4 * (kr & 3) + ((kr >> 2) & 1) + (((nc >> 3) & 1) << 1);

    const float* Ab = A + (size_t)(by * 128 + aRow) * K + aK0;
    const float* Bb = B + bx * 128 + nc + (size_t)kr * N;

    float acc[4][4][4];
#pragma unroll
    for (int i = 0; i < 4; i++)
#pragma unroll
        for (int j = 0; j < 4; j++)
#pragma unroll
            for (int r = 0; r < 4; r++) acc[i][j][r] = 0.0f;

    float4 ra0 = *(const float4*)(Ab);
    float4 ra1 = *(const float4*)(Ab + 4);
    float4 rb0 = *(const float4*)(Bb);
    float4 rb1 = *(const float4*)(Bb + 4);

    auto stage = [&](int nb, const float4& a0, const float4& a1,
                               const float4& b0, const float4& b1) {
        unsigned* Ad = Abuf[nb] + aBlk * NBLK + aPosB;
        // j = k - aK0 in 0..7: pos += 4*(j&3) + 2*((j>>2)&1)
        Ad[0]          = f2tf(a0.x);   // j=0: tg0 kh0
        Ad[4]          = f2tf(a0.y);   // j=1
        Ad[8]          = f2tf(a0.z);   // j=2
        Ad[12]         = f2tf(a0.w);   // j=3
        Ad[2]          = f2tf(a1.x);   // j=4: tg0 kh1
        Ad[6]          = f2tf(a1.y);
        Ad[10]         = f2tf(a1.z);
        Ad[14]         = f2tf(a1.w);
        unsigned* Bd = Bbuf[nb] + bBlk * NBLK + bPosB;
        // n = nc + jj: pos += 16*jj
        Bd[0]   = f2tf(b0.x);
        Bd[16]  = f2tf(b0.y);
        Bd[32]  = f2tf(b0.z);
        Bd[48]  = f2tf(b0.w);
        Bd[64]  = f2tf(b1.x);
        Bd[80]  = f2tf(b1.y);
        Bd[96]  = f2tf(b1.z);
        Bd[112] = f2tf(b1.w);
    };

    stage(0, ra0, ra1, rb0, rb1);
    __syncthreads();

    int buf = 0;
    for (int k0 = 0; k0 < K; k0 += 16) {
        const bool hasNext = (k0 + 16) < K;
        if (hasNext) {
            ra0 = *(const float4*)(Ab + k0 + 16);
            ra1 = *(const float4*)(Ab + k0 + 20);
            rb0 = *(const float4*)(Bb + (size_t)(k0 + 16) * N);
            rb1 = *(const float4*)(Bb + (size_t)(k0 + 16) * N + 4);
        }

        const unsigned* As = Abuf[buf];
        const unsigned* Bs = Bbuf[buf];
#pragma unroll
        for (int ks = 0; ks < 2; ks++) {
            unsigned af[4][4], bf[2][4];
#pragma unroll
            for (int i = 0; i < 4; i++)
                *(uint4*)af[i] =
                    *(const uint4*)&As[(wm * 8 + i * 2 + ks) * NBLK + lane * 4];
#pragma unroll
            for (int jp = 0; jp < 2; jp++)
                *(uint4*)bf[jp] =
                    *(const uint4*)&Bs[(wn * 4 + jp * 2 + ks) * NBLK + lane * 4];
#pragma unroll
            for (int i = 0; i < 4; i++)
#pragma unroll
                for (int jp = 0; jp < 2; jp++) {
                    MMA_TF32(acc[i][2 * jp],     af[i], (&bf[jp][0]));
                    MMA_TF32(acc[i][2 * jp + 1], af[i], (&bf[jp][2]));
                }
        }

        if (hasNext) stage(buf ^ 1, ra0, ra1, rb0, rb1);
        __syncthreads();
        buf ^= 1;
    }

    // ---- epilogue: bias + store
#pragma unroll
    for (int i = 0; i < 4; i++) {
        const int row = by * 128 + wm * 64 + i * 16 + g;
#pragma unroll
        for (int j = 0; j < 4; j++) {
            const int col = bx * 128 + wn * 32 + j * 8 + tg * 2;
            const float2 bv = *(const float2*)(bias + col);
            float2 o0, o1;
            o0.x = acc[i][j][0] + bv.x; o0.y = acc[i][j][1] + bv.y;
            o1.x = acc[i][j][2] + bv.x; o1.y = acc[i][j][3] + bv.y;
            *(float2*)(C + (size_t)row * N + col)       = o0;
            *(float2*)(C + (size_t)(row + 8) * N + col) = o1;
        }
    }
}

// ---------------- masked-row mean kernel ------------------------------------
// For rows q >= l[b], the reference's additive -1e8 mask quantizes every
// logit to exactly -1e8 in fp32, so softmax is exactly uniform and
// y_row = mean(V) over all T keys. Compute once per (b,h) and broadcast.
__global__ void __launch_bounds__(256) vmean_kernel(
    const float* __restrict__ qkv, const int* __restrict__ lv,
    float* __restrict__ y)
{
    const int b  = blockIdx.x >> 4;
    const int h  = blockIdx.x & 15;
    const int lb = lv[b];
    __shared__ float part[4][64];

    const int d = threadIdx.x & 63;
    const int c = threadIdx.x >> 6;
    const float* Vb = qkv + (size_t)b * 2048 * 3072 + 2048 + h * 64 + d;

    float s = 0.0f;
    const float* p = Vb + (size_t)(c * 512) * 3072;
#pragma unroll 8
    for (int t = 0; t < 512; t++) s += p[(size_t)t * 3072];
    part[c][d] = s;
    __syncthreads();

    if (threadIdx.x < 64) {
        part[0][d] = (part[0][d] + part[1][d] + part[2][d] + part[3][d])
                   * (1.0f / 2048.0f);
    }
    __syncthreads();

    const float m = part[0][d];
    for (int t = lb + c; t < 2048; t += 4)
        y[(size_t)(b * 2048 + t) * 1024 + h * 64 + d] = m;
}

// ---------------- tensor-core flash attention (causal rows only) -----------
#define LQK 68
#define LV  72

__global__ void __launch_bounds__(256, 2) attn_tc_kernel(
    const float* __restrict__ qkv,
    const int*   __restrict__ lv,
    float* __restrict__ y)
{
    extern __shared__ float sm[];
    unsigned* Qh = (unsigned*)sm;
    unsigned* Ql = Qh + 64 * LQK;
    unsigned* Kh = Ql + 64 * LQK;
    unsigned* Kl = Kh + 64 * LQK;
    unsigned* Vt = Kl + 64 * LQK;
    float*    Sp = (float*)(Vt + 64 * LV);
    float*    m_s = Sp + 64 * LQK;
    float*    l_s = m_s + 64;
    float*    a_s = l_s + 64;

    const int tid  = threadIdx.x;
    const int lane = tid & 31;
    const int wid  = tid >> 5;
    const int g    = lane >> 2;
    const int tg   = lane & 3;
    const int wm   = wid >> 1;
    const int wn   = wid & 1;

    const int bh = blockIdx.y;
    const int b  = bh >> 4;
    const int h  = bh & 15;
    const int q0 = blockIdx.x * 64;
    const int lb = lv[b];

    if (q0 >= lb) return;   // all rows masked -> handled by vmean_kernel

    const float* Qb = qkv + (size_t)b * 2048 * 3072 + h * 64;
    const float* Kb = Qb + 1024;
    const float* Vb = Qb + 2048;

    for (int i = tid; i < 64 * 16; i += 256) {
        int r  = i >> 4;
        int d4 = (i & 15) << 2;
        float4 v = *(const float4*)(Qb + (size_t)(q0 + r) * 3072 + d4);
        float vv[4] = {v.x, v.y, v.z, v.w};
#pragma unroll
        for (int c = 0; c < 4; c++) {
            unsigned hb = f2tf(vv[c]);
            Qh[r * LQK + d4 + c] = hb;
            Ql[r * LQK + d4 + c] = f2tf(vv[c] - __uint_as_float(hb));
        }
    }
    if (tid < 64) { m_s[tid] = -1e30f; l_s[tid] = 0.0f; }

    float oacc[4][4];
#pragma unroll
    for (int j = 0; j < 4; j++)
#pragma unroll
        for (int r = 0; r < 4; r++) oacc[j][r] = 0.0f;

    const int ra = wm * 16 + g;
    const int nTiles = blockIdx.x + 1;   // causal only

    for (int t = 0; t < nTiles; t++) {
        const int k0 = t * 64;
        __syncthreads();

        for (int i = tid; i < 64 * 16; i += 256) {
            int r  = i >> 4;
            int d4 = (i & 15) << 2;
            float4 kv = *(const float4*)(Kb + (size_t)(k0 + r) * 3072 + d4);
            float kk[4] = {kv.x, kv.y, kv.z, kv.w};
#pragma unroll
            for (int c = 0; c < 4; c++) {
                unsigned hb = f2tf(kk[c]);
                Kh[r * LQK + d4 + c] = hb;
                Kl[r * LQK + d4 + c] = f2tf(kk[c] - __uint_as_float(hb));
            }
            float4 vv = *(const float4*)(Vb + (size_t)(k0 + r) * 3072 + d4);
            Vt[r * LV + d4 + 0] = f2tf(vv.x);
            Vt[r * LV + d4 + 1] = f2tf(vv.y);
            Vt[r * LV + d4 + 2] = f2tf(vv.z);
            Vt[r * LV + d4 + 3] = f2tf(vv.w);
        }
        __syncthreads();

        float sacc[4][4];
#pragma unroll
        for (int j = 0; j < 4; j++)
#pragma unroll
            for (int r = 0; r < 4; r++) sacc[j][r] = 0.0f;

#pragma unroll
        for (int kd = 0; kd < 64; kd += 8) {
            unsigned ah[4], alo[4];
            ah[0]  = Qh[ra * LQK + kd + tg];
            ah[1]  = Qh[(ra + 8) * LQK + kd + tg];
            ah[2]  = Qh[ra * LQK + kd + tg + 4];
            ah[3]  = Qh[(ra + 8) * LQK + kd + tg + 4];
            alo[0] = Ql[ra * LQK + kd + tg];
            alo[1] = Ql[(ra + 8) * LQK + kd + tg];
            alo[2] = Ql[ra * LQK + kd + tg + 4];
            alo[3] = Ql[(ra + 8) * LQK + kd + tg + 4];
#pragma unroll
            for (int j = 0; j < 4; j++) {
                const int cb = wn * 32 + j * 8 + g;
                unsigned bh_[2], bl_[2];
                bh_[0] = Kh[cb * LQK + kd + tg];
                bh_[1] = Kh[cb * LQK + kd + tg + 4];
                bl_[0] = Kl[cb * LQK + kd + tg];
                bl_[1] = Kl[cb * LQK + kd + tg + 4];
                MMA_TF32(sacc[j], ah, bh_);
                MMA_TF32(sacc[j], ah, bl_);
                MMA_TF32(sacc[j], alo, bh_);
            }
        }

        const int qg0 = q0 + ra;
        const int qg1 = qg0 + 8;
#pragma unroll
        for (int j = 0; j < 4; j++) {
            const int kc = k0 + wn * 32 + j * 8 + 2 * tg;
            float v0 = sacc[j][0] * 0.125f;
            float v1 = sacc[j][1] * 0.125f;
            float v2 = sacc[j][2] * 0.125f;
            float v3 = sacc[j][3] * 0.125f;
            if (qg0 < lb) {
                if (kc > qg0)     v0 = -1e30f;
                if (kc + 1 > qg0) v1 = -1e30f;
            } else { v0 += -1e8f; v1 += -1e8f; }
            if (qg1 < lb) {
                if (kc > qg1)     v2 = -1e30f;
                if (kc + 1 > qg1) v3 = -1e30f;
            } else { v2 += -1e8f; v3 += -1e8f; }
            const int cl = wn * 32 + j * 8 + 2 * tg;
            Sp[ra * LQK + cl]           = v0;
            Sp[ra * LQK + cl + 1]       = v1;
            Sp[(ra + 8) * LQK + cl]     = v2;
            Sp[(ra + 8) * LQK + cl + 1] = v3;
        }
        __syncthreads();

        {
            const int r   = tid >> 2;
            const int sub = tid & 3;
            float* row = Sp + r * LQK + sub * 16;
            float mx = -1e30f;
#pragma unroll
            for (int c = 0; c < 16; c++) mx = fmaxf(mx, row[c]);
            mx = fmaxf(mx, __shfl_xor_sync(0xffffffffu, mx, 1));
            mx = fmaxf(mx, __shfl_xor_sync(0xffffffffu, mx, 2));
            const float m_old = m_s[r];
            const float m_new = fmaxf(m_old, mx);
            float sum = 0.0f;
#pragma unroll
            for (int c = 0; c < 16; c++) {
                float e = __expf(row[c] - m_new);
                sum += e;
                ((unsigned*)row)[c] = f2tf(e);
            }
            sum += __shfl_xor_sync(0xffffffffu, sum, 1);
            sum += __shfl_xor_sync(0xffffffffu, sum, 2);
            if (sub == 0) {
                const float alpha = __expf(m_old - m_new);
                l_s[r] = l_s[r] * alpha + sum;
                m_s[r] = m_new;
                a_s[r] = alpha;
            }
        }
        __syncthreads();

        const float al0 = a_s[ra];
        const float al1 = a_s[ra + 8];
#pragma unroll
        for (int j = 0; j < 4; j++) {
            oacc[j][0] *= al0; oacc[j][1] *= al0;
            oacc[j][2] *= al1; oacc[j][3] *= al1;
        }
        const unsigned* Pu = (const unsigned*)Sp;
#pragma unroll
        for (int kc = 0; kc < 64; kc += 8) {
            unsigned pa[4];
            pa[0] = Pu[ra * LQK + kc + tg];
            pa[1] = Pu[(ra + 8) * LQK + kc + tg];
            pa[2] = Pu[ra * LQK + kc + tg + 4];
            pa[3] = Pu[(ra + 8) * LQK + kc + tg + 4];
#pragma unroll
            for (int j = 0; j < 4; j++) {
                const int db = wn * 32 + j * 8 + g;
                unsigned bv[2];
                bv[0] = Vt[(kc + tg) * LV + db];
                bv[1] = Vt[(kc + tg + 4) * LV + db];
                MMA_TF32(oacc[j], pa, bv);
            }
        }
    }

    // store only rows q < lb (masked rows owned by vmean_kernel)
    const float inv0 = 1.0f / l_s[ra];
    const float inv1 = 1.0f / l_s[ra + 8];
    float* yr0 = y + (size_t)(b * 2048 + q0 + ra) * 1024 + h * 64;
    float* yr1 = y + (size_t)(b * 2048 + q0 + ra + 8) * 1024 + h * 64;
    const bool st0 = (q0 + ra)     < lb;
    const bool st1 = (q0 + ra + 8) < lb;
#pragma unroll
    for (int j = 0; j < 4; j++) {
        const int cl = wn * 32 + j * 8 + 2 * tg;
        if (st0) {
            float2 o0;
            o0.x = oacc[j][0] * inv0; o0.y = oacc[j][1] * inv0;
            *(float2*)(yr0 + cl) = o0;
        }
        if (st1) {
            float2 o1;
            o1.x = oacc[j][2] * inv1; o1.y = oacc[j][3] * inv1;
            *(float2*)(yr1 + cl) = o1;
        }
    }
}

// ---------------- launch ---------------------------------------------------
static const int ATTN_SMEM =
    (4 * 64 * LQK + 64 * LV + 64 * LQK + 3 * 64) * (int)sizeof(float);

extern "C" void kernel_launch(void* const* d_in, const int* in_sizes, int n_in,
                              void* d_out, int out_size)
{
    const float* x      = (const float*)d_in[0];
    const int*   l      = (const int*)  d_in[1];
    const float* W_attn = (const float*)d_in[2];
    const float* b_attn = (const float*)d_in[3];
    const float* W_proj = (const float*)d_in[4];
    const float* b_proj = (const float*)d_in[5];
    float* out = (float*)d_out;

    float* qkv = nullptr;
    float* yb  = nullptr;
    cudaGetSymbolAddress((void**)&qkv, g_qkv);
    cudaGetSymbolAddress((void**)&yb,  g_y);

    cudaFuncSetAttribute(attn_tc_kernel,
                         cudaFuncAttributeMaxDynamicSharedMemorySize, ATTN_SMEM);

    // 1) QKV = x @ W_attn + b_attn   (tf32 tensor cores)
    {
        dim3 grid(3072 / 128, 8192 / 128);
        sgemm_tf32_kernel<<<grid, 256>>>(x, W_attn, b_attn, qkv, 8192, 3072, 1024);
    }
    // 2a) masked-row means (rows q >= l)
    vmean_kernel<<<64, 256>>>(qkv, l, yb);
    // 2b) attention, causal rows only
    {
        dim3 grid(2048 / 64, 4 * 16);
        attn_tc_kernel<<<grid, 256, ATTN_SMEM>>>(qkv, l, yb);
    }
    // 3) out = y @ W_proj + b_proj   (tf32 tensor cores)
    {
        dim3 grid(1024 / 128, 8192 / 128);
        sgemm_tf32_kernel<<<grid, 256>>>(yb, W_proj, b_proj, out, 8192, 1024, 1024);
    }
}

// round 8
// speedup vs baseline: 4.7183x; 1.3480x over previous
#include <cuda_runtime.h>
#include <math.h>

// ---------------- scratch (device globals: allocation-guard safe) ----------
__device__ float    g_qkv[(size_t)8192 * 3072];    // [B*T, 3C] Q|K|V per row
__device__ float    g_y  [(size_t)8192 * 1024];    // [B*T, C]  attention output
__device__ unsigned g_xpack [(size_t)8192 * 1024]; // x packed (tf32 frag layout)
__device__ unsigned g_ypack [(size_t)8192 * 1024]; // y packed
__device__ unsigned g_wapack[(size_t)1024 * 3072]; // W_attn packed
__device__ unsigned g_wppack[(size_t)1024 * 1024]; // W_proj packed

// ---------------- tf32 helpers ---------------------------------------------
__device__ __forceinline__ unsigned f2tf(float f) {
    unsigned u;
    asm("cvt.rna.tf32.f32 %0, %1;" : "=r"(u) : "f"(f));
    return u;
}

#define MMA_TF32(d, av, bv)                                                   \
    asm volatile(                                                             \
        "mma.sync.aligned.m16n8k8.row.col.f32.tf32.tf32.f32 "                 \
        "{%0,%1,%2,%3},{%4,%5,%6,%7},{%8,%9},{%0,%1,%2,%3};"                  \
        : "+f"(d[0]), "+f"(d[1]), "+f"(d[2]), "+f"(d[3])                      \
        : "r"(av[0]), "r"(av[1]), "r"(av[2]), "r"(av[3]),                     \
          "r"(bv[0]), "r"(bv[1]))

// ---------------- fragment pack layout --------------------------------------
// A (left operand, row-major [M][K]) packed per 128-row tile mt, k8-slice s,
// sub-block sb=(m>>4)&7, 128 words = 32 lanes x 4 regs:
//   lane = 4*(m&7) + (k&3);  reg = ((m>>3)&1) + 2*((k>>2)&1)
// B (right operand, row-major [K][N]) packed per 128-col tile nt, slice s,
// sub-block sb=(n>>4)&7 (two n8 j-tiles per block):
//   lane = 4*(n&7) + (k&3);  reg = ((k>>2)&1) + 2*((n>>3)&1)
// word index = (((tile*KS + s)*8 + sb)*128 + lane*4 + reg),  KS = K/8.

__global__ void __launch_bounds__(256) pack_a_kernel(
    const float* __restrict__ A, unsigned* __restrict__ out, int K, int KS)
{
    const size_t i = (size_t)blockIdx.x * 256 + threadIdx.x; // one uint4/thread
    const int lane = (int)(i & 31);
    size_t rest = i >> 5;
    const int sb = (int)(rest & 7); rest >>= 3;
    const int s  = (int)(rest % KS);
    const int mt = (int)(rest / KS);
    const int m0 = mt * 128 + sb * 16 + (lane >> 2);
    const int k0 = s * 8 + (lane & 3);
    const float* a = A + (size_t)m0 * K + k0;
    uint4 o;
    o.x = f2tf(a[0]);
    o.y = f2tf(a[(size_t)8 * K]);
    o.z = f2tf(a[4]);
    o.w = f2tf(a[(size_t)8 * K + 4]);
    *(uint4*)(out + i * 4) = o;
}

__global__ void __launch_bounds__(256) pack_b_kernel(
    const float* __restrict__ W, unsigned* __restrict__ out, int N, int KS)
{
    const size_t i = (size_t)blockIdx.x * 256 + threadIdx.x;
    const int lane = (int)(i & 31);
    size_t rest = i >> 5;
    const int sb = (int)(rest & 7); rest >>= 3;
    const int s  = (int)(rest % KS);
    const int nt = (int)(rest / KS);
    const int n0 = nt * 128 + sb * 16 + (lane >> 2);
    const int k0 = s * 8 + (lane & 3);
    const float* w = W + (size_t)k0 * N + n0;
    uint4 o;
    o.x = f2tf(w[0]);
    o.y = f2tf(w[(size_t)4 * N]);
    o.z = f2tf(w[8]);
    o.w = f2tf(w[(size_t)4 * N + 8]);
    *(uint4*)(out + i * 4) = o;
}

// ---------------- packed-operand tf32 GEMM (no smem, no barriers) ----------
// 128x128 block tile, 8 warps, warp tile 64x32. Per k8 slice: 6 LDG.128
// (fragments direct from L2-resident packed panels) + 16 HMMA.
__global__ void __launch_bounds__(256, 2) gemm_packed_kernel(
    const unsigned* __restrict__ Ap, const unsigned* __restrict__ Bp,
    const float* __restrict__ bias, float* __restrict__ C, int N, int KS)
{
    const int tid  = threadIdx.x;
    const int lane = tid & 31;
    const int wid  = tid >> 5;
    const int wm   = wid & 1;
    const int wn   = wid >> 1;
    const int g    = lane >> 2;
    const int tg   = lane & 3;

    const unsigned* aw = Ap + (((size_t)blockIdx.y * KS) * 8 + wm * 4) * 128
                            + lane * 4;
    const unsigned* bw = Bp + (((size_t)blockIdx.x * KS) * 8 + wn * 2) * 128
                            + lane * 4;

    float acc[4][4][4];
#pragma unroll
    for (int i = 0; i < 4; i++)
#pragma unroll
        for (int j = 0; j < 4; j++)
#pragma unroll
            for (int r = 0; r < 4; r++) acc[i][j][r] = 0.0f;

#pragma unroll 4
    for (int s = 0; s < KS; s++) {
        unsigned af[4][4], bf[2][4];
#pragma unroll
        for (int i = 0; i < 4; i++)
            *(uint4*)af[i] = *(const uint4*)(aw + (size_t)(s * 8 + i) * 128);
#pragma unroll
        for (int jp = 0; jp < 2; jp++)
            *(uint4*)bf[jp] = *(const uint4*)(bw + (size_t)(s * 8 + jp) * 128);
#pragma unroll
        for (int i = 0; i < 4; i++)
#pragma unroll
            for (int jp = 0; jp < 2; jp++) {
                MMA_TF32(acc[i][2 * jp],     af[i], (&bf[jp][0]));
                MMA_TF32(acc[i][2 * jp + 1], af[i], (&bf[jp][2]));
            }
    }

    // ---- epilogue: bias + store (row-major C)
#pragma unroll
    for (int i = 0; i < 4; i++) {
        const int row = blockIdx.y * 128 + wm * 64 + i * 16 + g;
#pragma unroll
        for (int j = 0; j < 4; j++) {
            const int col = blockIdx.x * 128 + wn * 32 + j * 8 + tg * 2;
            const float2 bv = *(const float2*)(bias + col);
            float2 o0, o1;
            o0.x = acc[i][j][0] + bv.x; o0.y = acc[i][j][1] + bv.y;
            o1.x = acc[i][j][2] + bv.x; o1.y = acc[i][j][3] + bv.y;
            *(float2*)(C + (size_t)row * N + col)       = o0;
            *(float2*)(C + (size_t)(row + 8) * N + col) = o1;
        }
    }
}

// ---------------- masked-row mean kernel ------------------------------------
// For rows q >= l[b], the reference's additive -1e8 mask quantizes every
// logit to exactly -1e8 in fp32, so softmax is exactly uniform and
// y_row = mean(V) over all T keys. Compute once per (b,h) and broadcast.
__global__ void __launch_bounds__(256) vmean_kernel(
    const float* __restrict__ qkv, const int* __restrict__ lv,
    float* __restrict__ y)
{
    const int b  = blockIdx.x >> 4;
    const int h  = blockIdx.x & 15;
    const int lb = lv[b];
    __shared__ float part[4][64];

    const int d = threadIdx.x & 63;
    const int c = threadIdx.x >> 6;
    const float* Vb = qkv + (size_t)b * 2048 * 3072 + 2048 + h * 64 + d;

    float s = 0.0f;
    const float* p = Vb + (size_t)(c * 512) * 3072;
#pragma unroll 8
    for (int t = 0; t < 512; t++) s += p[(size_t)t * 3072];
    part[c][d] = s;
    __syncthreads();

    if (threadIdx.x < 64) {
        part[0][d] = (part[0][d] + part[1][d] + part[2][d] + part[3][d])
                   * (1.0f / 2048.0f);
    }
    __syncthreads();

    const float m = part[0][d];
    for (int t = lb + c; t < 2048; t += 4)
        y[(size_t)(b * 2048 + t) * 1024 + h * 64 + d] = m;
}

// ---------------- tensor-core flash attention (causal rows only) -----------
#define LQK 68
#define LV  72

__global__ void __launch_bounds__(256, 2) attn_tc_kernel(
    const float* __restrict__ qkv,
    const int*   __restrict__ lv,
    float* __restrict__ y)
{
    extern __shared__ float sm[];
    unsigned* Qh = (unsigned*)sm;
    unsigned* Ql = Qh + 64 * LQK;
    unsigned* Kh = Ql + 64 * LQK;
    unsigned* Kl = Kh + 64 * LQK;
    unsigned* Vt = Kl + 64 * LQK;
    float*    Sp = (float*)(Vt + 64 * LV);
    float*    m_s = Sp + 64 * LQK;
    float*    l_s = m_s + 64;
    float*    a_s = l_s + 64;

    const int tid  = threadIdx.x;
    const int lane = tid & 31;
    const int wid  = tid >> 5;
    const int g    = lane >> 2;
    const int tg   = lane & 3;
    const int wm   = wid >> 1;
    const int wn   = wid & 1;

    const int bh = blockIdx.y;
    const int b  = bh >> 4;
    const int h  = bh & 15;
    const int q0 = blockIdx.x * 64;
    const int lb = lv[b];

    if (q0 >= lb) return;   // all rows masked -> handled by vmean_kernel

    const float* Qb = qkv + (size_t)b * 2048 * 3072 + h * 64;
    const float* Kb = Qb + 1024;
    const float* Vb = Qb + 2048;

    for (int i = tid; i < 64 * 16; i += 256) {
        int r  = i >> 4;
        int d4 = (i & 15) << 2;
        float4 v = *(const float4*)(Qb + (size_t)(q0 + r) * 3072 + d4);
        float vv[4] = {v.x, v.y, v.z, v.w};
#pragma unroll
        for (int c = 0; c < 4; c++) {
            unsigned hb = f2tf(vv[c]);
            Qh[r * LQK + d4 + c] = hb;
            Ql[r * LQK + d4 + c] = f2tf(vv[c] - __uint_as_float(hb));
        }
    }
    if (tid < 64) { m_s[tid] = -1e30f; l_s[tid] = 0.0f; }

    float oacc[4][4];
#pragma unroll
    for (int j = 0; j < 4; j++)
#pragma unroll
        for (int r = 0; r < 4; r++) oacc[j][r] = 0.0f;

    const int ra = wm * 16 + g;
    const int nTiles = blockIdx.x + 1;   // causal only

    for (int t = 0; t < nTiles; t++) {
        const int k0 = t * 64;
        __syncthreads();

        for (int i = tid; i < 64 * 16; i += 256) {
            int r  = i >> 4;
            int d4 = (i & 15) << 2;
            float4 kv = *(const float4*)(Kb + (size_t)(k0 + r) * 3072 + d4);
            float kk[4] = {kv.x, kv.y, kv.z, kv.w};
#pragma unroll
            for (int c = 0; c < 4; c++) {
                unsigned hb = f2tf(kk[c]);
                Kh[r * LQK + d4 + c] = hb;
                Kl[r * LQK + d4 + c] = f2tf(kk[c] - __uint_as_float(hb));
            }
            float4 vv = *(const float4*)(Vb + (size_t)(k0 + r) * 3072 + d4);
            Vt[r * LV + d4 + 0] = f2tf(vv.x);
            Vt[r * LV + d4 + 1] = f2tf(vv.y);
            Vt[r * LV + d4 + 2] = f2tf(vv.z);
            Vt[r * LV + d4 + 3] = f2tf(vv.w);
        }
        __syncthreads();

        float sacc[4][4];
#pragma unroll
        for (int j = 0; j < 4; j++)
#pragma unroll
            for (int r = 0; r < 4; r++) sacc[j][r] = 0.0f;

#pragma unroll
        for (int kd = 0; kd < 64; kd += 8) {
            unsigned ah[4], alo[4];
            ah[0]  = Qh[ra * LQK + kd + tg];
            ah[1]  = Qh[(ra + 8) * LQK + kd + tg];
            ah[2]  = Qh[ra * LQK + kd + tg + 4];
            ah[3]  = Qh[(ra + 8) * LQK + kd + tg + 4];
            alo[0] = Ql[ra * LQK + kd + tg];
            alo[1] = Ql[(ra + 8) * LQK + kd + tg];
            alo[2] = Ql[ra * LQK + kd + tg + 4];
            alo[3] = Ql[(ra + 8) * LQK + kd + tg + 4];
#pragma unroll
            for (int j = 0; j < 4; j++) {
                const int cb = wn * 32 + j * 8 + g;
                unsigned bh_[2], bl_[2];
                bh_[0] = Kh[cb * LQK + kd + tg];
                bh_[1] = Kh[cb * LQK + kd + tg + 4];
                bl_[0] = Kl[cb * LQK + kd + tg];
                bl_[1] = Kl[cb * LQK + kd + tg + 4];
                MMA_TF32(sacc[j], ah, bh_);
                MMA_TF32(sacc[j], ah, bl_);
                MMA_TF32(sacc[j], alo, bh_);
            }
        }

        const int qg0 = q0 + ra;
        const int qg1 = qg0 + 8;
#pragma unroll
        for (int j = 0; j < 4; j++) {
            const int kc = k0 + wn * 32 + j * 8 + 2 * tg;
            float v0 = sacc[j][0] * 0.125f;
            float v1 = sacc[j][1] * 0.125f;
            float v2 = sacc[j][2] * 0.125f;
            float v3 = sacc[j][3] * 0.125f;
            if (qg0 < lb) {
                if (kc > qg0)     v0 = -1e30f;
                if (kc + 1 > qg0) v1 = -1e30f;
            } else { v0 += -1e8f; v1 += -1e8f; }
            if (qg1 < lb) {
                if (kc > qg1)     v2 = -1e30f;
                if (kc + 1 > qg1) v3 = -1e30f;
            } else { v2 += -1e8f; v3 += -1e8f; }
            const int cl = wn * 32 + j * 8 + 2 * tg;
            Sp[ra * LQK + cl]           = v0;
            Sp[ra * LQK + cl + 1]       = v1;
            Sp[(ra + 8) * LQK + cl]     = v2;
            Sp[(ra + 8) * LQK + cl + 1] = v3;
        }
        __syncthreads();

        {
            const int r   = tid >> 2;
            const int sub = tid & 3;
            float* row = Sp + r * LQK + sub * 16;
            float mx = -1e30f;
#pragma unroll
            for (int c = 0; c < 16; c++) mx = fmaxf(mx, row[c]);
            mx = fmaxf(mx, __shfl_xor_sync(0xffffffffu, mx, 1));
            mx = fmaxf(mx, __shfl_xor_sync(0xffffffffu, mx, 2));
            const float m_old = m_s[r];
            const float m_new = fmaxf(m_old, mx);
            float sum = 0.0f;
#pragma unroll
            for (int c = 0; c < 16; c++) {
                float e = __expf(row[c] - m_new);
                sum += e;
                ((unsigned*)row)[c] = f2tf(e);
            }
            sum += __shfl_xor_sync(0xffffffffu, sum, 1);
            sum += __shfl_xor_sync(0xffffffffu, sum, 2);
            if (sub == 0) {
                const float alpha = __expf(m_old - m_new);
                l_s[r] = l_s[r] * alpha + sum;
                m_s[r] = m_new;
                a_s[r] = alpha;
            }
        }
        __syncthreads();

        const float al0 = a_s[ra];
        const float al1 = a_s[ra + 8];
#pragma unroll
        for (int j = 0; j < 4; j++) {
            oacc[j][0] *= al0; oacc[j][1] *= al0;
            oacc[j][2] *= al1; oacc[j][3] *= al1;
        }
        const unsigned* Pu = (const unsigned*)Sp;
#pragma unroll
        for (int kc = 0; kc < 64; kc += 8) {
            unsigned pa[4];
            pa[0] = Pu[ra * LQK + kc + tg];
            pa[1] = Pu[(ra + 8) * LQK + kc + tg];
            pa[2] = Pu[ra * LQK + kc + tg + 4];
            pa[3] = Pu[(ra + 8) * LQK + kc + tg + 4];
#pragma unroll
            for (int j = 0; j < 4; j++) {
                const int db = wn * 32 + j * 8 + g;
                unsigned bv[2];
                bv[0] = Vt[(kc + tg) * LV + db];
                bv[1] = Vt[(kc + tg + 4) * LV + db];
                MMA_TF32(oacc[j], pa, bv);
            }
        }
    }

    // store only rows q < lb (masked rows owned by vmean_kernel)
    const float inv0 = 1.0f / l_s[ra];
    const float inv1 = 1.0f / l_s[ra + 8];
    float* yr0 = y + (size_t)(b * 2048 + q0 + ra) * 1024 + h * 64;
    float* yr1 = y + (size_t)(b * 2048 + q0 + ra + 8) * 1024 + h * 64;
    const bool st0 = (q0 + ra)     < lb;
    const bool st1 = (q0 + ra + 8) < lb;
#pragma unroll
    for (int j = 0; j < 4; j++) {
        const int cl = wn * 32 + j * 8 + 2 * tg;
        if (st0) {
            float2 o0;
            o0.x = oacc[j][0] * inv0; o0.y = oacc[j][1] * inv0;
            *(float2*)(yr0 + cl) = o0;
        }
        if (st1) {
            float2 o1;
            o1.x = oacc[j][2] * inv1; o1.y = oacc[j][3] * inv1;
            *(float2*)(yr1 + cl) = o1;
        }
    }
}

// ---------------- launch ---------------------------------------------------
static const int ATTN_SMEM =
    (4 * 64 * LQK + 64 * LV + 64 * LQK + 3 * 64) * (int)sizeof(float);

extern "C" void kernel_launch(void* const* d_in, const int* in_sizes, int n_in,
                              void* d_out, int out_size)
{
    const float* x      = (const float*)d_in[0];
    const int*   l      = (const int*)  d_in[1];
    const float* W_attn = (const float*)d_in[2];
    const float* b_attn = (const float*)d_in[3];
    const float* W_proj = (const float*)d_in[4];
    const float* b_proj = (const float*)d_in[5];
    float* out = (float*)d_out;

    float *qkv = nullptr, *yb = nullptr;
    unsigned *xp = nullptr, *yp = nullptr, *wap = nullptr, *wpp = nullptr;
    cudaGetSymbolAddress((void**)&qkv, g_qkv);
    cudaGetSymbolAddress((void**)&yb,  g_y);
    cudaGetSymbolAddress((void**)&xp,  g_xpack);
    cudaGetSymbolAddress((void**)&yp,  g_ypack);
    cudaGetSymbolAddress((void**)&wap, g_wapack);
    cudaGetSymbolAddress((void**)&wpp, g_wppack);

    cudaFuncSetAttribute(attn_tc_kernel,
                         cudaFuncAttributeMaxDynamicSharedMemorySize, ATTN_SMEM);

    // 0) pack operands into tf32 fragment layout
    pack_b_kernel<<<3072, 256>>>(W_attn, wap, 3072, 128);   // 1024x3072
    pack_b_kernel<<<1024, 256>>>(W_proj, wpp, 1024, 128);   // 1024x1024
    pack_a_kernel<<<8192, 256>>>(x, xp, 1024, 128);         // 8192x1024

    // 1) QKV = x @ W_attn + b_attn
    {
        dim3 grid(3072 / 128, 8192 / 128);
        gemm_packed_kernel<<<grid, 256>>>(xp, wap, b_attn, qkv, 3072, 128);
    }
    // 2a) masked-row means (rows q >= l)
    vmean_kernel<<<64, 256>>>(qkv, l, yb);
    // 2b) attention, causal rows only
    {
        dim3 grid(2048 / 64, 4 * 16);
        attn_tc_kernel<<<grid, 256, ATTN_SMEM>>>(qkv, l, yb);
    }
    // 3) out = y @ W_proj + b_proj
    pack_a_kernel<<<8192, 256>>>(yb, yp, 1024, 128);        // 8192x1024
    {
        dim3 grid(1024 / 128, 8192 / 128);
        gemm_packed_kernel<<<grid, 256>>>(yp, wpp, b_proj, out, 1024, 128);
    }
}

// round 9
// speedup vs baseline: 4.9749x; 1.0544x over previous
#include <cuda_runtime.h>
#include <math.h>

// ---------------- scratch (device globals: allocation-guard safe) ----------
__device__ float    g_qkv[(size_t)8192 * 3072];    // [B*T, 3C] Q|K|V per row
__device__ float    g_y  [(size_t)8192 * 1024];    // [B*T, C]  attention output
__device__ unsigned g_xpack [(size_t)8192 * 1024]; // x packed (tf32 frag layout)
__device__ unsigned g_ypack [(size_t)8192 * 1024]; // y packed
__device__ unsigned g_wapack[(size_t)1024 * 3072]; // W_attn packed
__device__ unsigned g_wppack[(size_t)1024 * 1024]; // W_proj packed

// ---------------- tf32 helpers ---------------------------------------------
__device__ __forceinline__ unsigned f2tf(float f) {
    unsigned u;
    asm("cvt.rna.tf32.f32 %0, %1;" : "=r"(u) : "f"(f));
    return u;
}

#define MMA_TF32(d, av, bv)                                                   \
    asm volatile(                                                             \
        "mma.sync.aligned.m16n8k8.row.col.f32.tf32.tf32.f32 "                 \
        "{%0,%1,%2,%3},{%4,%5,%6,%7},{%8,%9},{%0,%1,%2,%3};"                  \
        : "+f"(d[0]), "+f"(d[1]), "+f"(d[2]), "+f"(d[3])                      \
        : "r"(av[0]), "r"(av[1]), "r"(av[2]), "r"(av[3]),                     \
          "r"(bv[0]), "r"(bv[1]))

// ---------------- fragment pack layout --------------------------------------
// A (left operand, row-major [M][K]) packed per 128-row tile mt, k8-slice s,
// sub-block sb=(m>>4)&7, 128 words = 32 lanes x 4 regs:
//   lane = 4*(m&7) + (k&3);  reg = ((m>>3)&1) + 2*((k>>2)&1)
// B (right operand, row-major [K][N]) packed per 128-col tile nt, slice s,
// sub-block sb=(n>>4)&7 (two n8 j-tiles per block):
//   lane = 4*(n&7) + (k&3);  reg = ((k>>2)&1) + 2*((n>>3)&1)
// word index = (((tile*KS + s)*8 + sb)*128 + lane*4 + reg),  KS = K/8.

__global__ void __launch_bounds__(256) pack_a_kernel(
    const float* __restrict__ A, unsigned* __restrict__ out, int K, int KS)
{
    const size_t i = (size_t)blockIdx.x * 256 + threadIdx.x; // one uint4/thread
    const int lane = (int)(i & 31);
    size_t rest = i >> 5;
    const int sb = (int)(rest & 7); rest >>= 3;
    const int s  = (int)(rest % KS);
    const int mt = (int)(rest / KS);
    const int m0 = mt * 128 + sb * 16 + (lane >> 2);
    const int k0 = s * 8 + (lane & 3);
    const float* a = A + (size_t)m0 * K + k0;
    uint4 o;
    o.x = f2tf(a[0]);
    o.y = f2tf(a[(size_t)8 * K]);
    o.z = f2tf(a[4]);
    o.w = f2tf(a[(size_t)8 * K + 4]);
    *(uint4*)(out + i * 4) = o;
}

__global__ void __launch_bounds__(256) pack_b_kernel(
    const float* __restrict__ W, unsigned* __restrict__ out, int N, int KS)
{
    const size_t i = (size_t)blockIdx.x * 256 + threadIdx.x;
    const int lane = (int)(i & 31);
    size_t rest = i >> 5;
    const int sb = (int)(rest & 7); rest >>= 3;
    const int s  = (int)(rest % KS);
    const int nt = (int)(rest / KS);
    const int n0 = nt * 128 + sb * 16 + (lane >> 2);
    const int k0 = s * 8 + (lane & 3);
    const float* w = W + (size_t)k0 * N + n0;
    uint4 o;
    o.x = f2tf(w[0]);
    o.y = f2tf(w[(size_t)4 * N]);
    o.z = f2tf(w[8]);
    o.w = f2tf(w[(size_t)4 * N + 8]);
    *(uint4*)(out + i * 4) = o;
}

// ---------------- packed-operand tf32 GEMM ---------------------------------
// 128x128 block tile, 8 warps, warp tile 64x32. No smem/barriers; fragments
// stream from L2-resident packed panels. Register double-buffered pipeline:
// slice s+1 loads issue before slice s MMA block retires.
__global__ void __launch_bounds__(256, 2) gemm_packed_kernel(
    const unsigned* __restrict__ Ap, const unsigned* __restrict__ Bp,
    const float* __restrict__ bias, float* __restrict__ C, int N, int KS)
{
    const int tid  = threadIdx.x;
    const int lane = tid & 31;
    const int wid  = tid >> 5;
    const int wm   = wid & 1;
    const int wn   = wid >> 1;
    const int g    = lane >> 2;
    const int tg   = lane & 3;

    const unsigned* aw = Ap + (((size_t)blockIdx.y * KS) * 8 + wm * 4) * 128
                            + lane * 4;
    const unsigned* bw = Bp + (((size_t)blockIdx.x * KS) * 8 + wn * 2) * 128
                            + lane * 4;

    float acc[4][4][4];
#pragma unroll
    for (int i = 0; i < 4; i++)
#pragma unroll
        for (int j = 0; j < 4; j++)
#pragma unroll
            for (int r = 0; r < 4; r++) acc[i][j][r] = 0.0f;

    unsigned af0[4][4], bf0[2][4], af1[4][4], bf1[2][4];

#define LOADFRAG(af, bf, s)                                                   \
    do {                                                                      \
        _Pragma("unroll")                                                     \
        for (int i_ = 0; i_ < 4; i_++)                                        \
            *(uint4*)(af)[i_] =                                               \
                *(const uint4*)(aw + (size_t)((s) * 8 + i_) * 128);           \
        _Pragma("unroll")                                                     \
        for (int jp_ = 0; jp_ < 2; jp_++)                                     \
            *(uint4*)(bf)[jp_] =                                              \
                *(const uint4*)(bw + (size_t)((s) * 8 + jp_) * 128);          \
    } while (0)

#define MMABLOCK(af, bf)                                                      \
    do {                                                                      \
        _Pragma("unroll")                                                     \
        for (int i_ = 0; i_ < 4; i_++) {                                      \
            _Pragma("unroll")                                                 \
            for (int jp_ = 0; jp_ < 2; jp_++) {                               \
                MMA_TF32(acc[i_][2 * jp_],     (af)[i_], (&(bf)[jp_][0]));    \
                MMA_TF32(acc[i_][2 * jp_ + 1], (af)[i_], (&(bf)[jp_][2]));    \
            }                                                                 \
        }                                                                     \
    } while (0)

    LOADFRAG(af0, bf0, 0);
    for (int s = 0; s < KS; s += 2) {           // KS even
        LOADFRAG(af1, bf1, s + 1);
        MMABLOCK(af0, bf0);
        if (s + 2 < KS) LOADFRAG(af0, bf0, s + 2);
        MMABLOCK(af1, bf1);
    }
#undef LOADFRAG
#undef MMABLOCK

    // ---- epilogue: bias + store (row-major C)
#pragma unroll
    for (int i = 0; i < 4; i++) {
        const int row = blockIdx.y * 128 + wm * 64 + i * 16 + g;
#pragma unroll
        for (int j = 0; j < 4; j++) {
            const int col = blockIdx.x * 128 + wn * 32 + j * 8 + tg * 2;
            const float2 bv = *(const float2*)(bias + col);
            float2 o0, o1;
            o0.x = acc[i][j][0] + bv.x; o0.y = acc[i][j][1] + bv.y;
            o1.x = acc[i][j][2] + bv.x; o1.y = acc[i][j][3] + bv.y;
            *(float2*)(C + (size_t)row * N + col)       = o0;
            *(float2*)(C + (size_t)(row + 8) * N + col) = o1;
        }
    }
}

// ---------------- masked-row mean kernel ------------------------------------
// For rows q >= l[b], the reference's additive -1e8 mask quantizes every
// logit to exactly -1e8 in fp32, so softmax is exactly uniform and
// y_row = mean(V) over all T keys. Compute once per (b,h) and broadcast.
__global__ void __launch_bounds__(256) vmean_kernel(
    const float* __restrict__ qkv, const int* __restrict__ lv,
    float* __restrict__ y)
{
    const int b  = blockIdx.x >> 4;
    const int h  = blockIdx.x & 15;
    const int lb = lv[b];
    __shared__ float part[4][64];

    const int d = threadIdx.x & 63;
    const int c = threadIdx.x >> 6;
    const float* Vb = qkv + (size_t)b * 2048 * 3072 + 2048 + h * 64 + d;

    float s = 0.0f;
    const float* p = Vb + (size_t)(c * 512) * 3072;
#pragma unroll 8
    for (int t = 0; t < 512; t++) s += p[(size_t)t * 3072];
    part[c][d] = s;
    __syncthreads();

    if (threadIdx.x < 64) {
        part[0][d] = (part[0][d] + part[1][d] + part[2][d] + part[3][d])
                   * (1.0f / 2048.0f);
    }
    __syncthreads();

    const float m = part[0][d];
    for (int t = lb + c; t < 2048; t += 4)
        y[(size_t)(b * 2048 + t) * 1024 + h * 64 + d] = m;
}

// ---------------- tensor-core flash attention (causal rows only) -----------
#define LQK 68
#define LV  72

__global__ void __launch_bounds__(256, 2) attn_tc_kernel(
    const float* __restrict__ qkv,
    const int*   __restrict__ lv,
    float* __restrict__ y)
{
    extern __shared__ float sm[];
    unsigned* Qh = (unsigned*)sm;
    unsigned* Ql = Qh + 64 * LQK;
    unsigned* Kh = Ql + 64 * LQK;
    unsigned* Kl = Kh + 64 * LQK;
    unsigned* Vt = Kl + 64 * LQK;
    float*    Sp = (float*)(Vt + 64 * LV);
    float*    m_s = Sp + 64 * LQK;
    float*    l_s = m_s + 64;
    float*    a_s = l_s + 64;

    const int tid  = threadIdx.x;
    const int lane = tid & 31;
    const int wid  = tid >> 5;
    const int g    = lane >> 2;
    const int tg   = lane & 3;
    const int wm   = wid >> 1;
    const int wn   = wid & 1;

    const int bh = blockIdx.y;
    const int b  = bh >> 4;
    const int h  = bh & 15;
    const int q0 = blockIdx.x * 64;
    const int lb = lv[b];

    if (q0 >= lb) return;   // all rows masked -> handled by vmean_kernel

    const float* Qb = qkv + (size_t)b * 2048 * 3072 + h * 64;
    const float* Kb = Qb + 1024;
    const float* Vb = Qb + 2048;

    for (int i = tid; i < 64 * 16; i += 256) {
        int r  = i >> 4;
        int d4 = (i & 15) << 2;
        float4 v = *(const float4*)(Qb + (size_t)(q0 + r) * 3072 + d4);
        float vv[4] = {v.x, v.y, v.z, v.w};
#pragma unroll
        for (int c = 0; c < 4; c++) {
            unsigned hb = f2tf(vv[c]);
            Qh[r * LQK + d4 + c] = hb;
            Ql[r * LQK + d4 + c] = f2tf(vv[c] - __uint_as_float(hb));
        }
    }
    if (tid < 64) { m_s[tid] = -1e30f; l_s[tid] = 0.0f; }

    float oacc[4][4];
#pragma unroll
    for (int j = 0; j < 4; j++)
#pragma unroll
        for (int r = 0; r < 4; r++) oacc[j][r] = 0.0f;

    const int ra = wm * 16 + g;
    const int nTiles = blockIdx.x + 1;   // causal only

    for (int t = 0; t < nTiles; t++) {
        const int k0 = t * 64;
        __syncthreads();

        for (int i = tid; i < 64 * 16; i += 256) {
            int r  = i >> 4;
            int d4 = (i & 15) << 2;
            float4 kv = *(const float4*)(Kb + (size_t)(k0 + r) * 3072 + d4);
            float kk[4] = {kv.x, kv.y, kv.z, kv.w};
#pragma unroll
            for (int c = 0; c < 4; c++) {
                unsigned hb = f2tf(kk[c]);
                Kh[r * LQK + d4 + c] = hb;
                Kl[r * LQK + d4 + c] = f2tf(kk[c] - __uint_as_float(hb));
            }
            float4 vv = *(const float4*)(Vb + (size_t)(k0 + r) * 3072 + d4);
            Vt[r * LV + d4 + 0] = f2tf(vv.x);
            Vt[r * LV + d4 + 1] = f2tf(vv.y);
            Vt[r * LV + d4 + 2] = f2tf(vv.z);
            Vt[r * LV + d4 + 3] = f2tf(vv.w);
        }
        __syncthreads();

        float sacc[4][4];
#pragma unroll
        for (int j = 0; j < 4; j++)
#pragma unroll
            for (int r = 0; r < 4; r++) sacc[j][r] = 0.0f;

#pragma unroll
        for (int kd = 0; kd < 64; kd += 8) {
            unsigned ah[4], alo[4];
            ah[0]  = Qh[ra * LQK + kd + tg];
            ah[1]  = Qh[(ra + 8) * LQK + kd + tg];
            ah[2]  = Qh[ra * LQK + kd + tg + 4];
            ah[3]  = Qh[(ra + 8) * LQK + kd + tg + 4];
            alo[0] = Ql[ra * LQK + kd + tg];
            alo[1] = Ql[(ra + 8) * LQK + kd + tg];
            alo[2] = Ql[ra * LQK + kd + tg + 4];
            alo[3] = Ql[(ra + 8) * LQK + kd + tg + 4];
#pragma unroll
            for (int j = 0; j < 4; j++) {
                const int cb = wn * 32 + j * 8 + g;
                unsigned bh_[2], bl_[2];
                bh_[0] = Kh[cb * LQK + kd + tg];
                bh_[1] = Kh[cb * LQK + kd + tg + 4];
                bl_[0] = Kl[cb * LQK + kd + tg];
                bl_[1] = Kl[cb * LQK + kd + tg + 4];
                MMA_TF32(sacc[j], ah, bh_);
                MMA_TF32(sacc[j], ah, bl_);
                MMA_TF32(sacc[j], alo, bh_);
            }
        }

        const int qg0 = q0 + ra;
        const int qg1 = qg0 + 8;
#pragma unroll
        for (int j = 0; j < 4; j++) {
            const int kc = k0 + wn * 32 + j * 8 + 2 * tg;
            float v0 = sacc[j][0] * 0.125f;
            float v1 = sacc[j][1] * 0.125f;
            float v2 = sacc[j][2] * 0.125f;
            float v3 = sacc[j][3] * 0.125f;
            if (qg0 < lb) {
                if (kc > qg0)     v0 = -1e30f;
                if (kc + 1 > qg0) v1 = -1e30f;
            } else { v0 += -1e8f; v1 += -1e8f; }
            if (qg1 < lb) {
                if (kc > qg1)     v2 = -1e30f;
                if (kc + 1 > qg1) v3 = -1e30f;
            } else { v2 += -1e8f; v3 += -1e8f; }
            const int cl = wn * 32 + j * 8 + 2 * tg;
            Sp[ra * LQK + cl]           = v0;
            Sp[ra * LQK + cl + 1]       = v1;
            Sp[(ra + 8) * LQK + cl]     = v2;
            Sp[(ra + 8) * LQK + cl + 1] = v3;
        }
        __syncthreads();

        {
            const int r   = tid >> 2;
            const int sub = tid & 3;
            float* row = Sp + r * LQK + sub * 16;
            float mx = -1e30f;
#pragma unroll
            for (int c = 0; c < 16; c++) mx = fmaxf(mx, row[c]);
            mx = fmaxf(mx, __shfl_xor_sync(0xffffffffu, mx, 1));
            mx = fmaxf(mx, __shfl_xor_sync(0xffffffffu, mx, 2));
            const float m_old = m_s[r];
            const float m_new = fmaxf(m_old, mx);
            float sum = 0.0f;
#pragma unroll
            for (int c = 0; c < 16; c++) {
                float e = __expf(row[c] - m_new);
                sum += e;
                ((unsigned*)row)[c] = f2tf(e);
            }
            sum += __shfl_xor_sync(0xffffffffu, sum, 1);
            sum += __shfl_xor_sync(0xffffffffu, sum, 2);
            if (sub == 0) {
                const float alpha = __expf(m_old - m_new);
                l_s[r] = l_s[r] * alpha + sum;
                m_s[r] = m_new;
                a_s[r] = alpha;
            }
        }
        __syncthreads();

        const float al0 = a_s[ra];
        const float al1 = a_s[ra + 8];
#pragma unroll
        for (int j = 0; j < 4; j++) {
            oacc[j][0] *= al0; oacc[j][1] *= al0;
            oacc[j][2] *= al1; oacc[j][3] *= al1;
        }
        const unsigned* Pu = (const unsigned*)Sp;
#pragma unroll
        for (int kc = 0; kc < 64; kc += 8) {
            unsigned pa[4];
            pa[0] = Pu[ra * LQK + kc + tg];
            pa[1] = Pu[(ra + 8) * LQK + kc + tg];
            pa[2] = Pu[ra * LQK + kc + tg + 4];
            pa[3] = Pu[(ra + 8) * LQK + kc + tg + 4];
#pragma unroll
            for (int j = 0; j < 4; j++) {
                const int db = wn * 32 + j * 8 + g;
                unsigned bv[2];
                bv[0] = Vt[(kc + tg) * LV + db];
                bv[1] = Vt[(kc + tg + 4) * LV + db];
                MMA_TF32(oacc[j], pa, bv);
            }
        }
    }

    // store only rows q < lb (masked rows owned by vmean_kernel)
    const float inv0 = 1.0f / l_s[ra];
    const float inv1 = 1.0f / l_s[ra + 8];
    float* yr0 = y + (size_t)(b * 2048 + q0 + ra) * 1024 + h * 64;
    float* yr1 = y + (size_t)(b * 2048 + q0 + ra + 8) * 1024 + h * 64;
    const bool st0 = (q0 + ra)     < lb;
    const bool st1 = (q0 + ra + 8) < lb;
#pragma unroll
    for (int j = 0; j < 4; j++) {
        const int cl = wn * 32 + j * 8 + 2 * tg;
        if (st0) {
            float2 o0;
            o0.x = oacc[j][0] * inv0; o0.y = oacc[j][1] * inv0;
            *(float2*)(yr0 + cl) = o0;
        }
        if (st1) {
            float2 o1;
            o1.x = oacc[j][2] * inv1; o1.y = oacc[j][3] * inv1;
            *(float2*)(yr1 + cl) = o1;
        }
    }
}

// ---------------- launch ---------------------------------------------------
static const int ATTN_SMEM =
    (4 * 64 * LQK + 64 * LV + 64 * LQK + 3 * 64) * (int)sizeof(float);

extern "C" void kernel_launch(void* const* d_in, const int* in_sizes, int n_in,
                              void* d_out, int out_size)
{
    const float* x      = (const float*)d_in[0];
    const int*   l      = (const int*)  d_in[1];
    const float* W_attn = (const float*)d_in[2];
    const float* b_attn = (const float*)d_in[3];
    const float* W_proj = (const float*)d_in[4];
    const float* b_proj = (const float*)d_in[5];
    float* out = (float*)d_out;

    float *qkv = nullptr, *yb = nullptr;
    unsigned *xp = nullptr, *yp = nullptr, *wap = nullptr, *wpp = nullptr;
    cudaGetSymbolAddress((void**)&qkv, g_qkv);
    cudaGetSymbolAddress((void**)&yb,  g_y);
    cudaGetSymbolAddress((void**)&xp,  g_xpack);
    cudaGetSymbolAddress((void**)&yp,  g_ypack);
    cudaGetSymbolAddress((void**)&wap, g_wapack);
    cudaGetSymbolAddress((void**)&wpp, g_wppack);

    cudaFuncSetAttribute(attn_tc_kernel,
                         cudaFuncAttributeMaxDynamicSharedMemorySize, ATTN_SMEM);

    // 0) pack operands into tf32 fragment layout
    pack_b_kernel<<<3072, 256>>>(W_attn, wap, 3072, 128);   // 1024x3072
    pack_b_kernel<<<1024, 256>>>(W_proj, wpp, 1024, 128);   // 1024x1024
    pack_a_kernel<<<8192, 256>>>(x, xp, 1024, 128);         // 8192x1024

    // 1) QKV = x @ W_attn + b_attn
    {
        dim3 grid(3072 / 128, 8192 / 128);
        gemm_packed_kernel<<<grid, 256>>>(xp, wap, b_attn, qkv, 3072, 128);
    }
    // 2a) masked-row means (rows q >= l)
    vmean_kernel<<<64, 256>>>(qkv, l, yb);
    // 2b) attention, causal rows only
    {
        dim3 grid(2048 / 64, 4 * 16);
        attn_tc_kernel<<<grid, 256, ATTN_SMEM>>>(qkv, l, yb);
    }
    // 3) out = y @ W_proj + b_proj
    pack_a_kernel<<<8192, 256>>>(yb, yp, 1024, 128);        // 8192x1024
    {
        dim3 grid(1024 / 128, 8192 / 128);
        gemm_packed_kernel<<<grid, 256>>>(yp, wpp, b_proj, out, 1024, 128);
    }
}

// round 10
// speedup vs baseline: 5.1235x; 1.0299x over previous
#include <cuda_runtime.h>
#include <math.h>

// ---------------- scratch (device globals: allocation-guard safe) ----------
__device__ float    g_qkv[(size_t)8192 * 3072];    // [B*T, 3C] Q|K|V per row
__device__ float    g_y  [(size_t)8192 * 1024];    // [B*T, C]  attention output
__device__ unsigned g_xpack [(size_t)8192 * 1024]; // x packed (tf32 frag layout)
__device__ unsigned g_ypack [(size_t)8192 * 1024]; // y packed
__device__ unsigned g_wapack[(size_t)1024 * 3072]; // W_attn packed
__device__ unsigned g_wppack[(size_t)1024 * 1024]; // W_proj packed
__device__ unsigned g_khp[(size_t)64 * 128 * 8 * 128]; // K hi frags per (b,h)
__device__ unsigned g_klp[(size_t)64 * 128 * 8 * 128]; // K lo frags
__device__ unsigned g_vp [(size_t)64 * 4 * 256 * 128]; // V frags

// ---------------- tf32 helpers ---------------------------------------------
__device__ __forceinline__ unsigned f2tf(float f) {
    unsigned u;
    asm("cvt.rna.tf32.f32 %0, %1;" : "=r"(u) : "f"(f));
    return u;
}

#define MMA_TF32(d, av, bv)                                                   \
    asm volatile(                                                             \
        "mma.sync.aligned.m16n8k8.row.col.f32.tf32.tf32.f32 "                 \
        "{%0,%1,%2,%3},{%4,%5,%6,%7},{%8,%9},{%0,%1,%2,%3};"                  \
        : "+f"(d[0]), "+f"(d[1]), "+f"(d[2]), "+f"(d[3])                      \
        : "r"(av[0]), "r"(av[1]), "r"(av[2]), "r"(av[3]),                     \
          "r"(bv[0]), "r"(bv[1]))

// ---------------- fragment pack layout (see R7 notes) ------------------------
// B-layout block = 16 n x 8 k, 128 words: lane = 4*(n&7)+(k&3),
// reg = ((k>>2)&1) + 2*((n>>3)&1).
// A-layout block = 16 m x 8 k: lane = 4*(m&7)+(k&3), reg = ((m>>3)&1)+2*((k>>2)&1).

__global__ void __launch_bounds__(256) pack_a_kernel(
    const float* __restrict__ A, unsigned* __restrict__ out, int K, int KS)
{
    const size_t i = (size_t)blockIdx.x * 256 + threadIdx.x;
    const int lane = (int)(i & 31);
    size_t rest = i >> 5;
    const int sb = (int)(rest & 7); rest >>= 3;
    const int s  = (int)(rest % KS);
    const int mt = (int)(rest / KS);
    const int m0 = mt * 128 + sb * 16 + (lane >> 2);
    const int k0 = s * 8 + (lane & 3);
    const float* a = A + (size_t)m0 * K + k0;
    uint4 o;
    o.x = f2tf(a[0]);
    o.y = f2tf(a[(size_t)8 * K]);
    o.z = f2tf(a[4]);
    o.w = f2tf(a[(size_t)8 * K + 4]);
    *(uint4*)(out + i * 4) = o;
}

__global__ void __launch_bounds__(256) pack_b_kernel(
    const float* __restrict__ W, unsigned* __restrict__ out, int N, int KS)
{
    const size_t i = (size_t)blockIdx.x * 256 + threadIdx.x;
    const int lane = (int)(i & 31);
    size_t rest = i >> 5;
    const int sb = (int)(rest & 7); rest >>= 3;
    const int s  = (int)(rest % KS);
    const int nt = (int)(rest / KS);
    const int n0 = nt * 128 + sb * 16 + (lane >> 2);
    const int k0 = s * 8 + (lane & 3);
    const float* w = W + (size_t)k0 * N + n0;
    uint4 o;
    o.x = f2tf(w[0]);
    o.y = f2tf(w[(size_t)4 * N]);
    o.z = f2tf(w[8]);
    o.w = f2tf(w[(size_t)4 * N + 8]);
    *(uint4*)(out + i * 4) = o;
}

// K pack: B-layout over (n=key, k=d) with hi/lo tf32 split.
// block id = (bh*128 + kb16)*8 + s ; kb16 = key/16, s = d/8.
__global__ void __launch_bounds__(256) pack_k_kernel(
    const float* __restrict__ qkv,
    unsigned* __restrict__ kh, unsigned* __restrict__ kl)
{
    const size_t i = (size_t)blockIdx.x * 256 + threadIdx.x;
    const int lane = (int)(i & 31);
    size_t rest = i >> 5;
    const int s    = (int)(rest & 7);   rest >>= 3;
    const int kb16 = (int)(rest & 127); rest >>= 7;
    const int bh   = (int)rest;
    const int b = bh >> 4, h = bh & 15;
    const int key = kb16 * 16 + (lane >> 2);
    const int d   = s * 8 + (lane & 3);
    const float* src = qkv + (size_t)(b * 2048 + key) * 3072 + 1024 + h * 64 + d;
    float v0 = src[0];
    float v1 = src[4];
    float v2 = src[(size_t)8 * 3072];
    float v3 = src[(size_t)8 * 3072 + 4];
    uint4 hiw, low;
    hiw.x = f2tf(v0); low.x = f2tf(v0 - __uint_as_float(hiw.x));
    hiw.y = f2tf(v1); low.y = f2tf(v1 - __uint_as_float(hiw.y));
    hiw.z = f2tf(v2); low.z = f2tf(v2 - __uint_as_float(hiw.z));
    hiw.w = f2tf(v3); low.w = f2tf(v3 - __uint_as_float(hiw.w));
    *(uint4*)(kh + i * 4) = hiw;
    *(uint4*)(kl + i * 4) = low;
}

// V pack: B-layout over (n=d, k=key). block id = (bh*4 + nb16)*256 + ks.
__global__ void __launch_bounds__(256) pack_v_kernel(
    const float* __restrict__ qkv, unsigned* __restrict__ vp)
{
    const size_t i = (size_t)blockIdx.x * 256 + threadIdx.x;
    const int lane = (int)(i & 31);
    size_t rest = i >> 5;
    const int ks   = (int)(rest & 255); rest >>= 8;
    const int nb16 = (int)(rest & 3);   rest >>= 2;
    const int bh   = (int)rest;
    const int b = bh >> 4, h = bh & 15;
    const int d   = nb16 * 16 + (lane >> 2);
    const int key = ks * 8 + (lane & 3);
    const float* src = qkv + (size_t)(b * 2048 + key) * 3072 + 2048 + h * 64 + d;
    uint4 o;
    o.x = f2tf(src[0]);
    o.y = f2tf(src[(size_t)4 * 3072]);
    o.z = f2tf(src[8]);
    o.w = f2tf(src[(size_t)4 * 3072 + 8]);
    *(uint4*)(vp + i * 4) = o;
}

// ---------------- packed-operand tf32 GEMM (R8, unchanged) ------------------
__global__ void __launch_bounds__(256, 2) gemm_packed_kernel(
    const unsigned* __restrict__ Ap, const unsigned* __restrict__ Bp,
    const float* __restrict__ bias, float* __restrict__ C, int N, int KS)
{
    const int tid  = threadIdx.x;
    const int lane = tid & 31;
    const int wid  = tid >> 5;
    const int wm   = wid & 1;
    const int wn   = wid >> 1;
    const int g    = lane >> 2;
    const int tg   = lane & 3;

    const unsigned* aw = Ap + (((size_t)blockIdx.y * KS) * 8 + wm * 4) * 128
                            + lane * 4;
    const unsigned* bw = Bp + (((size_t)blockIdx.x * KS) * 8 + wn * 2) * 128
                            + lane * 4;

    float acc[4][4][4];
#pragma unroll
    for (int i = 0; i < 4; i++)
#pragma unroll
        for (int j = 0; j < 4; j++)
#pragma unroll
            for (int r = 0; r < 4; r++) acc[i][j][r] = 0.0f;

    unsigned af0[4][4], bf0[2][4], af1[4][4], bf1[2][4];

#define LOADFRAG(af, bf, s)                                                   \
    do {                                                                      \
        _Pragma("unroll")                                                     \
        for (int i_ = 0; i_ < 4; i_++)                                        \
            *(uint4*)(af)[i_] =                                               \
                *(const uint4*)(aw + (size_t)((s) * 8 + i_) * 128);           \
        _Pragma("unroll")                                                     \
        for (int jp_ = 0; jp_ < 2; jp_++)                                     \
            *(uint4*)(bf)[jp_] =                                              \
                *(const uint4*)(bw + (size_t)((s) * 8 + jp_) * 128);          \
    } while (0)

#define MMABLOCK(af, bf)                                                      \
    do {                                                                      \
        _Pragma("unroll")                                                     \
        for (int i_ = 0; i_ < 4; i_++) {                                      \
            _Pragma("unroll")                                                 \
            for (int jp_ = 0; jp_ < 2; jp_++) {                               \
                MMA_TF32(acc[i_][2 * jp_],     (af)[i_], (&(bf)[jp_][0]));    \
                MMA_TF32(acc[i_][2 * jp_ + 1], (af)[i_], (&(bf)[jp_][2]));    \
            }                                                                 \
        }                                                                     \
    } while (0)

    LOADFRAG(af0, bf0, 0);
    for (int s = 0; s < KS; s += 2) {
        LOADFRAG(af1, bf1, s + 1);
        MMABLOCK(af0, bf0);
        if (s + 2 < KS) LOADFRAG(af0, bf0, s + 2);
        MMABLOCK(af1, bf1);
    }
#undef LOADFRAG
#undef MMABLOCK

#pragma unroll
    for (int i = 0; i < 4; i++) {
        const int row = blockIdx.y * 128 + wm * 64 + i * 16 + g;
#pragma unroll
        for (int j = 0; j < 4; j++) {
            const int col = blockIdx.x * 128 + wn * 32 + j * 8 + tg * 2;
            const float2 bv = *(const float2*)(bias + col);
            float2 o0, o1;
            o0.x = acc[i][j][0] + bv.x; o0.y = acc[i][j][1] + bv.y;
            o1.x = acc[i][j][2] + bv.x; o1.y = acc[i][j][3] + bv.y;
            *(float2*)(C + (size_t)row * N + col)       = o0;
            *(float2*)(C + (size_t)(row + 8) * N + col) = o1;
        }
    }
}

// ---------------- masked-row mean kernel (unchanged) ------------------------
__global__ void __launch_bounds__(256) vmean_kernel(
    const float* __restrict__ qkv, const int* __restrict__ lv,
    float* __restrict__ y)
{
    const int b  = blockIdx.x >> 4;
    const int h  = blockIdx.x & 15;
    const int lb = lv[b];
    __shared__ float part[4][64];

    const int d = threadIdx.x & 63;
    const int c = threadIdx.x >> 6;
    const float* Vb = qkv + (size_t)b * 2048 * 3072 + 2048 + h * 64 + d;

    float s = 0.0f;
    const float* p = Vb + (size_t)(c * 512) * 3072;
#pragma unroll 8
    for (int t = 0; t < 512; t++) s += p[(size_t)t * 3072];
    part[c][d] = s;
    __syncthreads();

    if (threadIdx.x < 64) {
        part[0][d] = (part[0][d] + part[1][d] + part[2][d] + part[3][d])
                   * (1.0f / 2048.0f);
    }
    __syncthreads();

    const float m = part[0][d];
    for (int t = lb + c; t < 2048; t += 4)
        y[(size_t)(b * 2048 + t) * 1024 + h * 64 + d] = m;
}

// ---------------- flash attention with pre-packed K/V fragments -------------
#define LQK 68

__global__ void __launch_bounds__(256, 2) attn_tc_kernel(
    const float* __restrict__ qkv,
    const unsigned* __restrict__ Khp,
    const unsigned* __restrict__ Klp,
    const unsigned* __restrict__ Vp,
    const int*   __restrict__ lv,
    float* __restrict__ y)
{
    extern __shared__ float sm[];
    unsigned* Qh = (unsigned*)sm;          // [64][LQK]
    unsigned* Ql = Qh + 64 * LQK;
    float*    Sp = (float*)(Ql + 64 * LQK);
    float*    m_s = Sp + 64 * LQK;
    float*    l_s = m_s + 64;
    float*    a_s = l_s + 64;

    const int tid  = threadIdx.x;
    const int lane = tid & 31;
    const int wid  = tid >> 5;
    const int g    = lane >> 2;
    const int tg   = lane & 3;
    const int wm   = wid >> 1;
    const int wn   = wid & 1;

    const int bh = blockIdx.y;
    const int b  = bh >> 4;
    const int h  = bh & 15;
    const int q0 = blockIdx.x * 64;
    const int lb = lv[b];

    if (q0 >= lb) return;   // all rows masked -> handled by vmean_kernel

    const float* Qb = qkv + (size_t)b * 2048 * 3072 + h * 64;
    const unsigned* KhB = Khp + ((size_t)bh * 128 * 8) * 128 + lane * 4;
    const unsigned* KlB = Klp + ((size_t)bh * 128 * 8) * 128 + lane * 4;
    const unsigned* VB  = Vp  + ((size_t)bh * 4 * 256) * 128 + lane * 4;

    // ---- stage Q (hi/lo split) into smem
    for (int i = tid; i < 64 * 16; i += 256) {
        int r  = i >> 4;
        int d4 = (i & 15) << 2;
        float4 v = *(const float4*)(Qb + (size_t)(q0 + r) * 3072 + d4);
        float vv[4] = {v.x, v.y, v.z, v.w};
#pragma unroll
        for (int c = 0; c < 4; c++) {
            unsigned hb = f2tf(vv[c]);
            Qh[r * LQK + d4 + c] = hb;
            Ql[r * LQK + d4 + c] = f2tf(vv[c] - __uint_as_float(hb));
        }
    }
    if (tid < 64) { m_s[tid] = -1e30f; l_s[tid] = 0.0f; }
    __syncthreads();

    float oacc[4][4];
#pragma unroll
    for (int j = 0; j < 4; j++)
#pragma unroll
        for (int r = 0; r < 4; r++) oacc[j][r] = 0.0f;

    const int ra = wm * 16 + g;
    const int nTiles = blockIdx.x + 1;   // causal only

    for (int t = 0; t < nTiles; t++) {
        const int k0 = t * 64;

        // ---- S = Q K^T (split tf32: hh + hl + lh), K frags direct from gmem
        float sacc[4][4];
#pragma unroll
        for (int j = 0; j < 4; j++)
#pragma unroll
            for (int r = 0; r < 4; r++) sacc[j][r] = 0.0f;

#pragma unroll
        for (int s = 0; s < 8; s++) {
            const int kd = s * 8;
            unsigned ah[4], alo[4];
            ah[0]  = Qh[ra * LQK + kd + tg];
            ah[1]  = Qh[(ra + 8) * LQK + kd + tg];
            ah[2]  = Qh[ra * LQK + kd + tg + 4];
            ah[3]  = Qh[(ra + 8) * LQK + kd + tg + 4];
            alo[0] = Ql[ra * LQK + kd + tg];
            alo[1] = Ql[(ra + 8) * LQK + kd + tg];
            alo[2] = Ql[ra * LQK + kd + tg + 4];
            alo[3] = Ql[(ra + 8) * LQK + kd + tg + 4];
#pragma unroll
            for (int jp = 0; jp < 2; jp++) {
                const int kb16 = (k0 >> 4) + wn * 2 + jp;
                const size_t off = (size_t)(kb16 * 8 + s) * 128;
                uint4 bhf = *(const uint4*)(KhB + off);
                uint4 blf = *(const uint4*)(KlB + off);
                unsigned be[2]  = {bhf.x, bhf.y};
                unsigned bo[2]  = {bhf.z, bhf.w};
                unsigned ble[2] = {blf.x, blf.y};
                unsigned blo[2] = {blf.z, blf.w};
                MMA_TF32(sacc[2 * jp],     ah,  be);
                MMA_TF32(sacc[2 * jp],     ah,  ble);
                MMA_TF32(sacc[2 * jp],     alo, be);
                MMA_TF32(sacc[2 * jp + 1], ah,  bo);
                MMA_TF32(sacc[2 * jp + 1], ah,  blo);
                MMA_TF32(sacc[2 * jp + 1], alo, bo);
            }
        }

        __syncthreads();   // prev-tile PV done reading Sp

        // ---- mask + store S to smem (fp32)
        const int qg0 = q0 + ra;
        const int qg1 = qg0 + 8;
#pragma unroll
        for (int j = 0; j < 4; j++) {
            const int kc = k0 + wn * 32 + j * 8 + 2 * tg;
            float v0 = sacc[j][0] * 0.125f;
            float v1 = sacc[j][1] * 0.125f;
            float v2 = sacc[j][2] * 0.125f;
            float v3 = sacc[j][3] * 0.125f;
            if (qg0 < lb) {
                if (kc > qg0)     v0 = -1e30f;
                if (kc + 1 > qg0) v1 = -1e30f;
            } else { v0 += -1e8f; v1 += -1e8f; }
            if (qg1 < lb) {
                if (kc > qg1)     v2 = -1e30f;
                if (kc + 1 > qg1) v3 = -1e30f;
            } else { v2 += -1e8f; v3 += -1e8f; }
            const int cl = wn * 32 + j * 8 + 2 * tg;
            Sp[ra * LQK + cl]           = v0;
            Sp[ra * LQK + cl + 1]       = v1;
            Sp[(ra + 8) * LQK + cl]     = v2;
            Sp[(ra + 8) * LQK + cl + 1] = v3;
        }
        __syncthreads();

        // ---- online softmax: 4 threads per row
        {
            const int r   = tid >> 2;
            const int sub = tid & 3;
            float* row = Sp + r * LQK + sub * 16;
            float mx = -1e30f;
#pragma unroll
            for (int c = 0; c < 16; c++) mx = fmaxf(mx, row[c]);
            mx = fmaxf(mx, __shfl_xor_sync(0xffffffffu, mx, 1));
            mx = fmaxf(mx, __shfl_xor_sync(0xffffffffu, mx, 2));
            const float m_old = m_s[r];
            const float m_new = fmaxf(m_old, mx);
            float sum = 0.0f;
#pragma unroll
            for (int c = 0; c < 16; c++) {
                float e = __expf(row[c] - m_new);
                sum += e;
                ((unsigned*)row)[c] = f2tf(e);
            }
            sum += __shfl_xor_sync(0xffffffffu, sum, 1);
            sum += __shfl_xor_sync(0xffffffffu, sum, 2);
            if (sub == 0) {
                const float alpha = __expf(m_old - m_new);
                l_s[r] = l_s[r] * alpha + sum;
                m_s[r] = m_new;
                a_s[r] = alpha;
            }
        }
        __syncthreads();

        // ---- O = O*alpha + P V, V frags direct from gmem
        const float al0 = a_s[ra];
        const float al1 = a_s[ra + 8];
#pragma unroll
        for (int j = 0; j < 4; j++) {
            oacc[j][0] *= al0; oacc[j][1] *= al0;
            oacc[j][2] *= al1; oacc[j][3] *= al1;
        }
        const unsigned* Pu = (const unsigned*)Sp;
#pragma unroll
        for (int ks = 0; ks < 8; ks++) {
            const int kc = ks * 8;
            unsigned pa[4];
            pa[0] = Pu[ra * LQK + kc + tg];
            pa[1] = Pu[(ra + 8) * LQK + kc + tg];
            pa[2] = Pu[ra * LQK + kc + tg + 4];
            pa[3] = Pu[(ra + 8) * LQK + kc + tg + 4];
#pragma unroll
            for (int np = 0; np < 2; np++) {
                const int nb16 = wn * 2 + np;
                const size_t off = (size_t)(nb16 * 256 + (k0 >> 3) + ks) * 128;
                uint4 vf = *(const uint4*)(VB + off);
                unsigned ve[2] = {vf.x, vf.y};
                unsigned vo[2] = {vf.z, vf.w};
                MMA_TF32(oacc[2 * np],     pa, ve);
                MMA_TF32(oacc[2 * np + 1], pa, vo);
            }
        }
    }

    // ---- store only rows q < lb (masked rows owned by vmean_kernel)
    const float inv0 = 1.0f / l_s[ra];
    const float inv1 = 1.0f / l_s[ra + 8];
    float* yr0 = y + (size_t)(b * 2048 + q0 + ra) * 1024 + h * 64;
    float* yr1 = y + (size_t)(b * 2048 + q0 + ra + 8) * 1024 + h * 64;
    const bool st0 = (q0 + ra)     < lb;
    const bool st1 = (q0 + ra + 8) < lb;
#pragma unroll
    for (int j = 0; j < 4; j++) {
        const int cl = wn * 32 + j * 8 + 2 * tg;
        if (st0) {
            float2 o0;
            o0.x = oacc[j][0] * inv0; o0.y = oacc[j][1] * inv0;
            *(float2*)(yr0 + cl) = o0;
        }
        if (st1) {
            float2 o1;
            o1.x = oacc[j][2] * inv1; o1.y = oacc[j][3] * inv1;
            *(float2*)(yr1 + cl) = o1;
        }
    }
}

// ---------------- launch ---------------------------------------------------
static const int ATTN_SMEM = (3 * 64 * LQK + 3 * 64) * (int)sizeof(float);

extern "C" void kernel_launch(void* const* d_in, const int* in_sizes, int n_in,
                              void* d_out, int out_size)
{
    const float* x      = (const float*)d_in[0];
    const int*   l      = (const int*)  d_in[1];
    const float* W_attn = (const float*)d_in[2];
    const float* b_attn = (const float*)d_in[3];
    const float* W_proj = (const float*)d_in[4];
    const float* b_proj = (const float*)d_in[5];
    float* out = (float*)d_out;

    float *qkv = nullptr, *yb = nullptr;
    unsigned *xp = nullptr, *yp = nullptr, *wap = nullptr, *wpp = nullptr;
    unsigned *khp = nullptr, *klp = nullptr, *vp = nullptr;
    cudaGetSymbolAddress((void**)&qkv, g_qkv);
    cudaGetSymbolAddress((void**)&yb,  g_y);
    cudaGetSymbolAddress((void**)&xp,  g_xpack);
    cudaGetSymbolAddress((void**)&yp,  g_ypack);
    cudaGetSymbolAddress((void**)&wap, g_wapack);
    cudaGetSymbolAddress((void**)&wpp, g_wppack);
    cudaGetSymbolAddress((void**)&khp, g_khp);
    cudaGetSymbolAddress((void**)&klp, g_klp);
    cudaGetSymbolAddress((void**)&vp,  g_vp);

    cudaFuncSetAttribute(attn_tc_kernel,
                         cudaFuncAttributeMaxDynamicSharedMemorySize, ATTN_SMEM);

    // 0) pack GEMM operands
    pack_b_kernel<<<3072, 256>>>(W_attn, wap, 3072, 128);
    pack_b_kernel<<<1024, 256>>>(W_proj, wpp, 1024, 128);
    pack_a_kernel<<<8192, 256>>>(x, xp, 1024, 128);

    // 1) QKV = x @ W_attn + b_attn
    {
        dim3 grid(3072 / 128, 8192 / 128);
        gemm_packed_kernel<<<grid, 256>>>(xp, wap, b_attn, qkv, 3072, 128);
    }
    // 1b) pack K (hi/lo) and V into fragment layout
    pack_k_kernel<<<8192, 256>>>(qkv, khp, klp);
    pack_v_kernel<<<8192, 256>>>(qkv, vp);

    // 2a) masked-row means (rows q >= l)
    vmean_kernel<<<64, 256>>>(qkv, l, yb);
    // 2b) attention, causal rows only
    {
        dim3 grid(2048 / 64, 4 * 16);
        attn_tc_kernel<<<grid, 256, ATTN_SMEM>>>(qkv, khp, klp, vp, l, yb);
    }
    // 3) out = y @ W_proj + b_proj
    pack_a_kernel<<<8192, 256>>>(yb, yp, 1024, 128);
    {
        dim3 grid(1024 / 128, 8192 / 128);
        gemm_packed_kernel<<<grid, 256>>>(yp, wpp, b_proj, out, 1024, 128);
    }
}